// round 11
// baseline (speedup 1.0000x reference)
#include <cuda_runtime.h>
#include <cuda_bf16.h>
#include <cstdint>

// RBF-kernel causal attention via warp-level mma.sync (bf16, hi/lo compensated).
// Round 11: 256 threads / 8 warps per CTA, BM=128 (16 query rows per warp ==
// R7's proven per-warp micro-tile, so no register growth), 64-key tiles.
// 16 warps/SM to fill tensor-pipe gaps; K/V cp traffic halves.
// B=2, H=16, N=2048, D=64.

#define N_   2048
#define D_   64
#define BM   128
#define BN   64
#define NTH  256
#define LDH  72                      // halves per bf16 smem row (144 B)
#define CEXP 0.18033688011112042f    // log2(e)/8

#define MAT    9216                  // 64 rows * 144 B
#define B_KH   0
#define B_KL   MAT
#define B_VH   (2*MAT)
#define B_VL   (3*MAT)
#define B_KSQ  (4*MAT)
#define BUF    (4*MAT + 256)         // 37120
#define OFF_QSQ (2*BUF)              // 74240 (128 floats)
#define SMEM_BYTES (OFF_QSQ + 512)   // 74752

#define TOT4 (2*16*2048*16)          // float4 count per tensor

typedef uint32_t u32;

__device__ uint2 g_KH[TOT4];
__device__ uint2 g_KL[TOT4];
__device__ uint2 g_VH[TOT4];
__device__ uint2 g_VL[TOT4];
__device__ float g_ksq[2*16*2048];

__device__ __forceinline__ u32 smem_u32(const void* p) {
    u32 a;
    asm("{ .reg .u64 t; cvta.to.shared.u64 t, %1; cvt.u32.u64 %0, t; }"
        : "=r"(a) : "l"(p));
    return a;
}
__device__ __forceinline__ float ex2(float x) {
    float y; asm("ex2.approx.f32 %0, %1;" : "=f"(y) : "f"(x)); return y;
}
__device__ __forceinline__ void cp16(u32 saddr, const void* g) {
    asm volatile("cp.async.cg.shared.global [%0], [%1], 16;"
                 :: "r"(saddr), "l"(g) : "memory");
}
__device__ __forceinline__ void cp_commit() {
    asm volatile("cp.async.commit_group;" ::: "memory");
}
__device__ __forceinline__ void cp_wait0() {
    asm volatile("cp.async.wait_group 0;" ::: "memory");
}
__device__ __forceinline__ void ldsm4(u32 addr, u32 r[4]) {
    asm volatile("ldmatrix.sync.aligned.m8n8.x4.shared.b16 {%0,%1,%2,%3}, [%4];"
                 : "=r"(r[0]), "=r"(r[1]), "=r"(r[2]), "=r"(r[3]) : "r"(addr));
}
__device__ __forceinline__ void ldsm4t(u32 addr, u32 r[4]) {
    asm volatile("ldmatrix.sync.aligned.m8n8.x4.trans.shared.b16 {%0,%1,%2,%3}, [%4];"
                 : "=r"(r[0]), "=r"(r[1]), "=r"(r[2]), "=r"(r[3]) : "r"(addr));
}
__device__ __forceinline__ void mma16816(float d[4], const u32 a[4], u32 b0, u32 b1) {
    asm volatile(
        "mma.sync.aligned.m16n8k16.row.col.f32.bf16.bf16.f32 "
        "{%0,%1,%2,%3}, {%4,%5,%6,%7}, {%8,%9}, {%0,%1,%2,%3};"
        : "+f"(d[0]), "+f"(d[1]), "+f"(d[2]), "+f"(d[3])
        : "r"(a[0]), "r"(a[1]), "r"(a[2]), "r"(a[3]), "r"(b0), "r"(b1));
}
__device__ __forceinline__ u32 bits2(__nv_bfloat162 h) { return *(u32*)&h; }

__device__ __forceinline__ void split4(float4 v, uint2& hi, uint2& lo) {
    __nv_bfloat162 h0 = __floats2bfloat162_rn(v.x, v.y);
    __nv_bfloat162 h1 = __floats2bfloat162_rn(v.z, v.w);
    float2 f0 = __bfloat1622float2(h0);
    float2 f1 = __bfloat1622float2(h1);
    __nv_bfloat162 l0 = __floats2bfloat162_rn(v.x - f0.x, v.y - f0.y);
    __nv_bfloat162 l1 = __floats2bfloat162_rn(v.z - f1.x, v.w - f1.y);
    hi = make_uint2(bits2(h0), bits2(h1));
    lo = make_uint2(bits2(l0), bits2(l1));
}
__device__ __forceinline__ void cvt_store(char* smc, int off_hi, int off_lo, float4 v) {
    uint2 hi, lo;
    split4(v, hi, lo);
    *(uint2*)(smc + off_hi) = hi;
    *(uint2*)(smc + off_lo) = lo;
}

// ---------------- prep: f32 K/V -> bf16 hi/lo globals + ksq ----------------
__global__ void __launch_bounds__(256)
prep_kernel(const float* __restrict__ K, const float* __restrict__ V)
{
    const int i = blockIdx.x * 256 + threadIdx.x;     // float4 index
    float4 k = ((const float4*)K)[i];
    float4 v = ((const float4*)V)[i];
    uint2 hi, lo;
    split4(k, hi, lo);
    g_KH[i] = hi; g_KL[i] = lo;
    split4(v, hi, lo);
    g_VH[i] = hi; g_VL[i] = lo;

    float s = fmaf(k.x, k.x, fmaf(k.y, k.y, fmaf(k.z, k.z, k.w * k.w)));
    s += __shfl_xor_sync(0xffffffffu, s, 1, 16);
    s += __shfl_xor_sync(0xffffffffu, s, 2, 16);
    s += __shfl_xor_sync(0xffffffffu, s, 4, 16);
    s += __shfl_xor_sync(0xffffffffu, s, 8, 16);
    if ((threadIdx.x & 15) == 0) g_ksq[i >> 4] = s;
}

// cp.async one full key-tile (KH,KL,VH,VL + ksq) into smem buffer at dst (256 thr)
__device__ __forceinline__ void cp_tile(u32 dst, size_t rowbase, int tid)
{
    const char* khg = (const char*)g_KH + rowbase * 128;
    const char* klg = (const char*)g_KL + rowbase * 128;
    const char* vhg = (const char*)g_VH + rowbase * 128;
    const char* vlg = (const char*)g_VL + rowbase * 128;
#pragma unroll
    for (int i = 0; i < 2; i++) {
        int c   = i * 256 + tid;        // 0..511
        int row = c >> 3;
        int c8  = c & 7;
        u32 so  = (u32)(row * 144 + c8 * 16);
        size_t go = (size_t)row * 128 + (size_t)c8 * 16;
        cp16(dst + B_KH + so, khg + go);
        cp16(dst + B_KL + so, klg + go);
        cp16(dst + B_VH + so, vhg + go);
        cp16(dst + B_VL + so, vlg + go);
    }
    if (tid < 16)
        cp16(dst + B_KSQ + (u32)(tid * 16), (const char*)(g_ksq + rowbase) + tid * 16);
}

// ---------------- main kernel ----------------
__global__ void __launch_bounds__(NTH, 2)
rbf_attn_mma(const float* __restrict__ Qg, float* __restrict__ Og)
{
    extern __shared__ char smc[];
    const u32 sb  = smem_u32(smc);
    const int tid = threadIdx.x;
    const int w   = tid >> 5;            // 0..7
    const int t   = tid & 31;
    const int bh  = blockIdx.y;
    const int qt  = (gridDim.x - 1) - blockIdx.x;    // heavy tiles first
    const int m0  = qt * BM;
    const int nkt = 2 * qt + 2;

    const float* Qh = Qg + (size_t)bh * N_ * D_;
    float*       Oh = Og + (size_t)bh * N_ * D_;

    // ---- prologue: cp tile 0 into buffer 0 ----
    cp_tile(sb, (size_t)bh * N_, tid);
    cp_commit();

    // ---- stage Q (hi/lo bf16, 128 rows) into buffer 1, compute qsq ----
    {
        const float4* Q4 = (const float4*)(Qh + (size_t)m0 * D_);
#pragma unroll
        for (int i = 0; i < 8; i++) {
            int fidx = i * NTH + tid;            // 0..2047
            int row  = fidx >> 4;
            int c4   = (fidx & 15) << 2;
            cvt_store(smc, BUF + (row * LDH + c4) * 2,
                           BUF + 18432 + (row * LDH + c4) * 2, Q4[fidx]);
        }
        if (tid < BM) {
            float s = 0.f;
            const float4* Qr = (const float4*)(Qh + (size_t)(m0 + tid) * D_);
#pragma unroll
            for (int j = 0; j < 16; j++) {
                float4 v = Qr[j];
                s = fmaf(v.x, v.x, fmaf(v.y, v.y, fmaf(v.z, v.z, fmaf(v.w, v.w, s))));
            }
            ((float*)(smc + OFF_QSQ))[tid] = s;
        }
    }
    __syncthreads();

    // ---- extract Q A-fragments (16 rows per warp, persist in regs) ----
    u32 qa[4][4], ql[4][4];
    {
        const int row = w * 16 + (((t >> 3) & 1) << 3) + (t & 7);
        const int cg  = (t >> 4) << 3;
#pragma unroll
        for (int kc = 0; kc < 4; kc++) {
            u32 addr = sb + BUF + (u32)((row * LDH + 16 * kc + cg) * 2);
            ldsm4(addr, qa[kc]);
            ldsm4(addr + 18432, ql[kc]);
        }
    }
    const float q0 = ((float*)(smc + OFF_QSQ))[w * 16 + (t >> 2)];
    const float q1 = ((float*)(smc + OFF_QSQ))[w * 16 + (t >> 2) + 8];
    const int m_r0 = m0 + w * 16 + (t >> 2);
    const int m_r1 = m_r0 + 8;

    float o[8][4];
#pragma unroll
    for (int i = 0; i < 8; i++)
#pragma unroll
        for (int j = 0; j < 4; j++) o[i][j] = 0.f;
    float l0 = 0.f, l1 = 0.f;

    for (int kt = 0; kt < nkt; kt++) {
        const int n0 = kt * BN;
        const u32 cb = sb + (u32)((kt & 1) * BUF);
        const char* cc = smc + (size_t)((kt & 1) * BUF);
        const bool diag = (kt >= 2 * qt);

        cp_wait0();
        __syncthreads();

        if (kt + 1 < nkt)
            cp_tile(sb + (u32)(((kt + 1) & 1) * BUF),
                    (size_t)bh * N_ + (size_t)(n0 + BN), tid);
        cp_commit();

        // ---- prefetch ksq pairs into registers ----
        float2 kkr[8];
        {
            const float* ksq = (const float*)(cc + B_KSQ);
#pragma unroll
            for (int nb = 0; nb < 8; nb++)
                kkr[nb] = *(const float2*)&ksq[8 * nb + 2 * (t & 3)];
        }

        // ---- S = Q.K^T : pairs of nb chains, interleaved MMA issue ----
        float s[8][4];
#pragma unroll
        for (int i = 0; i < 8; i++)
#pragma unroll
            for (int j = 0; j < 4; j++) s[i][j] = 0.f;

        u32 kb[2][4], kl[2][4];
#pragma unroll
        for (int it = 0; it < 8; it++) {
            const int g = it >> 2, pair = it & 3;
            const int nb0 = 2 * pair, nb1 = nb0 + 1;
            {
                u32 a0 = cb + (u32)(((8 * nb0 + (t & 7)) * LDH
                                     + 32 * g + ((t >> 3) << 3)) * 2);
                u32 a1 = a0 + (u32)(8 * LDH * 2);
                ldsm4(a0, kb[0]);
                ldsm4(a1, kb[1]);
                ldsm4(a0 + MAT, kl[0]);
                ldsm4(a1 + MAT, kl[1]);
            }
            mma16816(s[nb0], qa[2*g],   kb[0][0], kb[0][1]);
            mma16816(s[nb1], qa[2*g],   kb[1][0], kb[1][1]);
            mma16816(s[nb0], qa[2*g+1], kb[0][2], kb[0][3]);
            mma16816(s[nb1], qa[2*g+1], kb[1][2], kb[1][3]);
            mma16816(s[nb0], qa[2*g],   kl[0][0], kl[0][1]);
            mma16816(s[nb1], qa[2*g],   kl[1][0], kl[1][1]);
            mma16816(s[nb0], qa[2*g+1], kl[0][2], kl[0][3]);
            mma16816(s[nb1], qa[2*g+1], kl[1][2], kl[1][3]);
            mma16816(s[nb0], ql[2*g],   kb[0][0], kb[0][1]);
            mma16816(s[nb1], ql[2*g],   kb[1][0], kb[1][1]);
            mma16816(s[nb0], ql[2*g+1], kb[0][2], kb[0][3]);
            mma16816(s[nb1], ql[2*g+1], kb[1][2], kb[1][3]);
        }

        // ==== 32-key halves: softmax(h) then PV(h) ====
#pragma unroll
        for (int h = 0; h < 2; h++) {
#pragma unroll
            for (int nb = 4 * h; nb < 4 * h + 4; nb++) {
                float2 kk = kkr[nb];
                float c0 = -CEXP * (q0 + kk.x);
                float c1 = -CEXP * (q0 + kk.y);
                float c2 = -CEXP * (q1 + kk.x);
                float c3 = -CEXP * (q1 + kk.y);
                float p0 = ex2(fminf(fmaf(s[nb][0], 2.f * CEXP, c0), 0.f));
                float p1 = ex2(fminf(fmaf(s[nb][1], 2.f * CEXP, c1), 0.f));
                float p2 = ex2(fminf(fmaf(s[nb][2], 2.f * CEXP, c2), 0.f));
                float p3 = ex2(fminf(fmaf(s[nb][3], 2.f * CEXP, c3), 0.f));
                if (diag) {
                    int nE = n0 + 8 * nb + 2 * (t & 3);
                    if (nE     > m_r0) p0 = 0.f;
                    if (nE + 1 > m_r0) p1 = 0.f;
                    if (nE     > m_r1) p2 = 0.f;
                    if (nE + 1 > m_r1) p3 = 0.f;
                }
                l0 += p0 + p1;
                l1 += p2 + p3;
                s[nb][0] = p0; s[nb][1] = p1;
                s[nb][2] = p2; s[nb][3] = p3;
            }

            // ---- PV for this half: cvt P, then nd-pairs interleaved ----
            u32 pha[2][4], pla[2][4];
#pragma unroll
            for (int c = 0; c < 2; c++) {
                const float* f0 = s[2 * (2*h + c)];
                const float* f1 = s[2 * (2*h + c) + 1];
                __nv_bfloat162 H0 = __floats2bfloat162_rn(f0[0], f0[1]);
                __nv_bfloat162 H1 = __floats2bfloat162_rn(f0[2], f0[3]);
                __nv_bfloat162 H2 = __floats2bfloat162_rn(f1[0], f1[1]);
                __nv_bfloat162 H3 = __floats2bfloat162_rn(f1[2], f1[3]);
                float2 g0 = __bfloat1622float2(H0);
                float2 g1 = __bfloat1622float2(H1);
                float2 g2 = __bfloat1622float2(H2);
                float2 g3 = __bfloat1622float2(H3);
                pha[c][0] = bits2(H0); pha[c][1] = bits2(H1);
                pha[c][2] = bits2(H2); pha[c][3] = bits2(H3);
                pla[c][0] = bits2(__floats2bfloat162_rn(f0[0]-g0.x, f0[1]-g0.y));
                pla[c][1] = bits2(__floats2bfloat162_rn(f0[2]-g1.x, f0[3]-g1.y));
                pla[c][2] = bits2(__floats2bfloat162_rn(f1[0]-g2.x, f1[1]-g2.y));
                pla[c][3] = bits2(__floats2bfloat162_rn(f1[2]-g3.x, f1[3]-g3.y));
            }
            const u32 vrow = cb + B_VH +
                (u32)(((32 * h + ((t >> 3) << 3) + (t & 7)) * LDH) * 2);
            u32 vh[2][4], vl[2][4];
#pragma unroll
            for (int pr = 0; pr < 4; pr++) {
                const int nd0 = 2 * pr, nd1 = nd0 + 1;
                {
                    u32 a0 = vrow + (u32)((8 * nd0) * 2);
                    u32 a1 = vrow + (u32)((8 * nd1) * 2);
                    ldsm4t(a0, vh[0]);
                    ldsm4t(a1, vh[1]);
                    ldsm4t(a0 + MAT, vl[0]);
                    ldsm4t(a1 + MAT, vl[1]);
                }
                mma16816(o[nd0], pha[0], vh[0][0], vh[0][1]);
                mma16816(o[nd1], pha[0], vh[1][0], vh[1][1]);
                mma16816(o[nd0], pha[1], vh[0][2], vh[0][3]);
                mma16816(o[nd1], pha[1], vh[1][2], vh[1][3]);
                mma16816(o[nd0], pha[0], vl[0][0], vl[0][1]);
                mma16816(o[nd1], pha[0], vl[1][0], vl[1][1]);
                mma16816(o[nd0], pha[1], vl[0][2], vl[0][3]);
                mma16816(o[nd1], pha[1], vl[1][2], vl[1][3]);
                mma16816(o[nd0], pla[0], vh[0][0], vh[0][1]);
                mma16816(o[nd1], pla[0], vh[1][0], vh[1][1]);
                mma16816(o[nd0], pla[1], vh[0][2], vh[0][3]);
                mma16816(o[nd1], pla[1], vh[1][2], vh[1][3]);
            }
        }
    }

    // ---- reduce l across the 4-lane quad sharing each row ----
    l0 += __shfl_xor_sync(0xffffffffu, l0, 1);
    l0 += __shfl_xor_sync(0xffffffffu, l0, 2);
    l1 += __shfl_xor_sync(0xffffffffu, l1, 1);
    l1 += __shfl_xor_sync(0xffffffffu, l1, 2);
    const float inv0 = 1.0f / l0;
    const float inv1 = 1.0f / l1;

    // ---- write O ----
#pragma unroll
    for (int nd = 0; nd < 8; nd++) {
        int dcol = 8 * nd + 2 * (t & 3);
        *(float2*)&Oh[(size_t)m_r0 * D_ + dcol] =
            make_float2(o[nd][0] * inv0, o[nd][1] * inv0);
        *(float2*)&Oh[(size_t)m_r1 * D_ + dcol] =
            make_float2(o[nd][2] * inv1, o[nd][3] * inv1);
    }
}

extern "C" void kernel_launch(void* const* d_in, const int* in_sizes, int n_in,
                              void* d_out, int out_size)
{
    const float* q = (const float*)d_in[0];
    const float* k = (const float*)d_in[1];
    const float* v = (const float*)d_in[2];
    float* o = (float*)d_out;
    (void)in_sizes; (void)n_in; (void)out_size;

    prep_kernel<<<TOT4 / 256, 256>>>(k, v);

    cudaFuncSetAttribute(rbf_attn_mma,
                         cudaFuncAttributeMaxDynamicSharedMemorySize, SMEM_BYTES);

    dim3 grid(N_ / BM, 32);
    rbf_attn_mma<<<grid, NTH, SMEM_BYTES>>>(q, o);
}

// round 12
// speedup vs baseline: 1.1927x; 1.1927x over previous
#include <cuda_runtime.h>
#include <cuda_bf16.h>
#include <cstdint>

// RBF-kernel causal attention via warp-level mma.sync (bf16, hi/lo compensated).
// Round 12: R10 base (BM=64, 4 warps, prep kernel, cp.async double buffer),
// mainloop restructured into 4 quarter-pipelined stages of 16 keys:
//   [QK(p) -> softmax(p) -> PV(p)] x 4
// QK(p+1) independent of PV(p) -> fine-grained tensor/ALU overlap; and the
// live softmax state shrinks from s[8][4] (32 regs) to s0,s1 (8 regs).
// B=2, H=16, N=2048, D=64.

#define N_   2048
#define D_   64
#define BM   64
#define BN   64
#define NTH  128
#define LDH  72                      // halves per bf16 smem row (144 B)
#define CEXP 0.18033688011112042f    // log2(e)/8

#define MAT    9216                  // 64 rows * 144 B
#define B_KH   0
#define B_KL   MAT
#define B_VH   (2*MAT)
#define B_VL   (3*MAT)
#define B_KSQ  (4*MAT)
#define BUF    (4*MAT + 256)         // 37120
#define OFF_QSQ (2*BUF)              // 74240
#define SMEM_BYTES (OFF_QSQ + 256)   // 74496

#define TOT4 (2*16*2048*16)          // float4 count per tensor

typedef uint32_t u32;

__device__ uint2 g_KH[TOT4];
__device__ uint2 g_KL[TOT4];
__device__ uint2 g_VH[TOT4];
__device__ uint2 g_VL[TOT4];
__device__ float g_ksq[2*16*2048];

__device__ __forceinline__ u32 smem_u32(const void* p) {
    u32 a;
    asm("{ .reg .u64 t; cvta.to.shared.u64 t, %1; cvt.u32.u64 %0, t; }"
        : "=r"(a) : "l"(p));
    return a;
}
__device__ __forceinline__ float ex2(float x) {
    float y; asm("ex2.approx.f32 %0, %1;" : "=f"(y) : "f"(x)); return y;
}
__device__ __forceinline__ void cp16(u32 saddr, const void* g) {
    asm volatile("cp.async.cg.shared.global [%0], [%1], 16;"
                 :: "r"(saddr), "l"(g) : "memory");
}
__device__ __forceinline__ void cp_commit() {
    asm volatile("cp.async.commit_group;" ::: "memory");
}
__device__ __forceinline__ void cp_wait0() {
    asm volatile("cp.async.wait_group 0;" ::: "memory");
}
__device__ __forceinline__ void ldsm4(u32 addr, u32 r[4]) {
    asm volatile("ldmatrix.sync.aligned.m8n8.x4.shared.b16 {%0,%1,%2,%3}, [%4];"
                 : "=r"(r[0]), "=r"(r[1]), "=r"(r[2]), "=r"(r[3]) : "r"(addr));
}
__device__ __forceinline__ void ldsm4t(u32 addr, u32 r[4]) {
    asm volatile("ldmatrix.sync.aligned.m8n8.x4.trans.shared.b16 {%0,%1,%2,%3}, [%4];"
                 : "=r"(r[0]), "=r"(r[1]), "=r"(r[2]), "=r"(r[3]) : "r"(addr));
}
__device__ __forceinline__ void mma16816(float d[4], const u32 a[4], u32 b0, u32 b1) {
    asm volatile(
        "mma.sync.aligned.m16n8k16.row.col.f32.bf16.bf16.f32 "
        "{%0,%1,%2,%3}, {%4,%5,%6,%7}, {%8,%9}, {%0,%1,%2,%3};"
        : "+f"(d[0]), "+f"(d[1]), "+f"(d[2]), "+f"(d[3])
        : "r"(a[0]), "r"(a[1]), "r"(a[2]), "r"(a[3]), "r"(b0), "r"(b1));
}
__device__ __forceinline__ u32 bits2(__nv_bfloat162 h) { return *(u32*)&h; }

__device__ __forceinline__ void split4(float4 v, uint2& hi, uint2& lo) {
    __nv_bfloat162 h0 = __floats2bfloat162_rn(v.x, v.y);
    __nv_bfloat162 h1 = __floats2bfloat162_rn(v.z, v.w);
    float2 f0 = __bfloat1622float2(h0);
    float2 f1 = __bfloat1622float2(h1);
    __nv_bfloat162 l0 = __floats2bfloat162_rn(v.x - f0.x, v.y - f0.y);
    __nv_bfloat162 l1 = __floats2bfloat162_rn(v.z - f1.x, v.w - f1.y);
    hi = make_uint2(bits2(h0), bits2(h1));
    lo = make_uint2(bits2(l0), bits2(l1));
}
__device__ __forceinline__ void cvt_store(char* smc, int off_hi, int off_lo, float4 v) {
    uint2 hi, lo;
    split4(v, hi, lo);
    *(uint2*)(smc + off_hi) = hi;
    *(uint2*)(smc + off_lo) = lo;
}

// ---------------- prep: f32 K/V -> bf16 hi/lo globals + ksq ----------------
__global__ void __launch_bounds__(256)
prep_kernel(const float* __restrict__ K, const float* __restrict__ V)
{
    const int i = blockIdx.x * 256 + threadIdx.x;     // float4 index
    float4 k = ((const float4*)K)[i];
    float4 v = ((const float4*)V)[i];
    uint2 hi, lo;
    split4(k, hi, lo);
    g_KH[i] = hi; g_KL[i] = lo;
    split4(v, hi, lo);
    g_VH[i] = hi; g_VL[i] = lo;

    float s = fmaf(k.x, k.x, fmaf(k.y, k.y, fmaf(k.z, k.z, k.w * k.w)));
    s += __shfl_xor_sync(0xffffffffu, s, 1, 16);
    s += __shfl_xor_sync(0xffffffffu, s, 2, 16);
    s += __shfl_xor_sync(0xffffffffu, s, 4, 16);
    s += __shfl_xor_sync(0xffffffffu, s, 8, 16);
    if ((threadIdx.x & 15) == 0) g_ksq[i >> 4] = s;
}

// cp.async one full key-tile (KH,KL,VH,VL + ksq) into smem buffer at dst
__device__ __forceinline__ void cp_tile(u32 dst, size_t rowbase, int tid)
{
    const char* khg = (const char*)g_KH + rowbase * 128;
    const char* klg = (const char*)g_KL + rowbase * 128;
    const char* vhg = (const char*)g_VH + rowbase * 128;
    const char* vlg = (const char*)g_VL + rowbase * 128;
#pragma unroll
    for (int i = 0; i < 4; i++) {
        int c   = i * 128 + tid;        // 0..511
        int row = c >> 3;
        int c8  = c & 7;
        u32 so  = (u32)(row * 144 + c8 * 16);
        size_t go = (size_t)row * 128 + (size_t)c8 * 16;
        cp16(dst + B_KH + so, khg + go);
        cp16(dst + B_KL + so, klg + go);
        cp16(dst + B_VH + so, vhg + go);
        cp16(dst + B_VL + so, vlg + go);
    }
    if (tid < 16)
        cp16(dst + B_KSQ + (u32)(tid * 16), (const char*)(g_ksq + rowbase) + tid * 16);
}

// ---------------- main kernel ----------------
__global__ void __launch_bounds__(NTH, 3)
rbf_attn_mma(const float* __restrict__ Qg, float* __restrict__ Og)
{
    extern __shared__ char smc[];
    const u32 sb  = smem_u32(smc);
    const int tid = threadIdx.x;
    const int w   = tid >> 5;
    const int t   = tid & 31;
    const int bh  = blockIdx.y;
    const int qt  = (gridDim.x - 1) - blockIdx.x;    // heavy tiles first
    const int m0  = qt * BM;
    const int nkt = qt + 1;

    const float* Qh = Qg + (size_t)bh * N_ * D_;
    float*       Oh = Og + (size_t)bh * N_ * D_;

    // ---- prologue: cp tile 0 into buffer 0 ----
    cp_tile(sb, (size_t)bh * N_, tid);
    cp_commit();

    // ---- stage Q (hi/lo bf16) into buffer 1, compute qsq ----
    {
        const float4* Q4 = (const float4*)(Qh + (size_t)m0 * D_);
#pragma unroll
        for (int i = 0; i < 8; i++) {
            int fidx = i * NTH + tid;
            int row  = fidx >> 4;
            int c4   = (fidx & 15) << 2;
            cvt_store(smc, BUF + B_KH + (row * LDH + c4) * 2,
                           BUF + B_KL + (row * LDH + c4) * 2, Q4[fidx]);
        }
        if (tid < BM) {
            float s = 0.f;
            const float4* Qr = (const float4*)(Qh + (size_t)(m0 + tid) * D_);
#pragma unroll
            for (int j = 0; j < 16; j++) {
                float4 v = Qr[j];
                s = fmaf(v.x, v.x, fmaf(v.y, v.y, fmaf(v.z, v.z, fmaf(v.w, v.w, s))));
            }
            ((float*)(smc + OFF_QSQ))[tid] = s;
        }
    }
    __syncthreads();

    // ---- extract Q A-fragments (persist in regs across all tiles) ----
    u32 qa[4][4], ql[4][4];
    {
        const int row = w * 16 + (((t >> 3) & 1) << 3) + (t & 7);
        const int cg  = (t >> 4) << 3;
#pragma unroll
        for (int kc = 0; kc < 4; kc++) {
            u32 addr = sb + BUF + B_KH + (u32)((row * LDH + 16 * kc + cg) * 2);
            ldsm4(addr, qa[kc]);
            ldsm4(addr + MAT, ql[kc]);
        }
    }
    const float q0 = ((float*)(smc + OFF_QSQ))[w * 16 + (t >> 2)];
    const float q1 = ((float*)(smc + OFF_QSQ))[w * 16 + (t >> 2) + 8];
    const int m_r0 = m0 + w * 16 + (t >> 2);
    const int m_r1 = m_r0 + 8;

    float o[8][4];
#pragma unroll
    for (int i = 0; i < 8; i++)
#pragma unroll
        for (int j = 0; j < 4; j++) o[i][j] = 0.f;
    float l0 = 0.f, l1 = 0.f;

    for (int kt = 0; kt < nkt; kt++) {
        const int n0 = kt * BN;
        const u32 cb = sb + (u32)((kt & 1) * BUF);
        const char* cc = smc + (size_t)((kt & 1) * BUF);
        const bool diag = (kt == qt);

        cp_wait0();
        __syncthreads();

        if (kt + 1 < nkt)
            cp_tile(sb + (u32)(((kt + 1) & 1) * BUF),
                    (size_t)bh * N_ + (size_t)(n0 + BN), tid);
        cp_commit();

        // per-thread base addresses for this tile
        const u32 kbase = cb + (u32)((((t & 7)) * LDH + ((t >> 3) << 3)) * 2);
        const u32 vbase = cb + B_VH +
            (u32)(((((t >> 3) & 1) << 3) + (t & 7)) * LDH * 2 + (((t >> 4) << 3)) * 2);
        const float* ksq = (const float*)(cc + B_KSQ);

        // ==== 4 quarter-pipelined stages of 16 keys each ====
#pragma unroll
        for (int p = 0; p < 4; p++) {
            const int nb0 = 2 * p, nb1 = nb0 + 1;

            // ---- QK(p): s0,s1 over keys 16p..16p+15, 3 compensated passes ----
            float s0[4] = {0.f, 0.f, 0.f, 0.f};
            float s1[4] = {0.f, 0.f, 0.f, 0.f};
#pragma unroll
            for (int g = 0; g < 2; g++) {
                u32 a0 = kbase + (u32)((8 * nb0 * LDH + 32 * g) * 2);
                u32 a1 = a0 + (u32)(8 * LDH * 2);
                u32 kb0[4], kb1[4], kl0[4], kl1[4];
                ldsm4(a0, kb0);
                ldsm4(a1, kb1);
                ldsm4(a0 + MAT, kl0);
                ldsm4(a1 + MAT, kl1);
                mma16816(s0, qa[2*g],   kb0[0], kb0[1]);
                mma16816(s1, qa[2*g],   kb1[0], kb1[1]);
                mma16816(s0, qa[2*g+1], kb0[2], kb0[3]);
                mma16816(s1, qa[2*g+1], kb1[2], kb1[3]);
                mma16816(s0, qa[2*g],   kl0[0], kl0[1]);
                mma16816(s1, qa[2*g],   kl1[0], kl1[1]);
                mma16816(s0, qa[2*g+1], kl0[2], kl0[3]);
                mma16816(s1, qa[2*g+1], kl1[2], kl1[3]);
                mma16816(s0, ql[2*g],   kb0[0], kb0[1]);
                mma16816(s1, ql[2*g],   kb1[0], kb1[1]);
                mma16816(s0, ql[2*g+1], kb0[2], kb0[3]);
                mma16816(s1, ql[2*g+1], kb1[2], kb1[3]);
            }

            // ---- softmax(p) on s0 (nb0) and s1 (nb1) ----
            {
                float2 kk0 = *(const float2*)&ksq[8 * nb0 + 2 * (t & 3)];
                float2 kk1 = *(const float2*)&ksq[8 * nb1 + 2 * (t & 3)];
                float p00 = ex2(fminf(fmaf(s0[0], 2.f*CEXP, -CEXP*(q0+kk0.x)), 0.f));
                float p01 = ex2(fminf(fmaf(s0[1], 2.f*CEXP, -CEXP*(q0+kk0.y)), 0.f));
                float p02 = ex2(fminf(fmaf(s0[2], 2.f*CEXP, -CEXP*(q1+kk0.x)), 0.f));
                float p03 = ex2(fminf(fmaf(s0[3], 2.f*CEXP, -CEXP*(q1+kk0.y)), 0.f));
                float p10 = ex2(fminf(fmaf(s1[0], 2.f*CEXP, -CEXP*(q0+kk1.x)), 0.f));
                float p11 = ex2(fminf(fmaf(s1[1], 2.f*CEXP, -CEXP*(q0+kk1.y)), 0.f));
                float p12 = ex2(fminf(fmaf(s1[2], 2.f*CEXP, -CEXP*(q1+kk1.x)), 0.f));
                float p13 = ex2(fminf(fmaf(s1[3], 2.f*CEXP, -CEXP*(q1+kk1.y)), 0.f));
                if (diag) {
                    int n0e = n0 + 8 * nb0 + 2 * (t & 3);
                    int n1e = n0 + 8 * nb1 + 2 * (t & 3);
                    if (n0e     > m_r0) p00 = 0.f;
                    if (n0e + 1 > m_r0) p01 = 0.f;
                    if (n0e     > m_r1) p02 = 0.f;
                    if (n0e + 1 > m_r1) p03 = 0.f;
                    if (n1e     > m_r0) p10 = 0.f;
                    if (n1e + 1 > m_r0) p11 = 0.f;
                    if (n1e     > m_r1) p12 = 0.f;
                    if (n1e + 1 > m_r1) p13 = 0.f;
                }
                l0 += (p00 + p01) + (p10 + p11);
                l1 += (p02 + p03) + (p12 + p13);
                s0[0] = p00; s0[1] = p01; s0[2] = p02; s0[3] = p03;
                s1[0] = p10; s1[1] = p11; s1[2] = p12; s1[3] = p13;
            }

            // ---- PV(p): k16 A-fragment from s0,s1, 3 compensated passes ----
            u32 pha[4], pla[4];
            {
                __nv_bfloat162 H0 = __floats2bfloat162_rn(s0[0], s0[1]);
                __nv_bfloat162 H1 = __floats2bfloat162_rn(s0[2], s0[3]);
                __nv_bfloat162 H2 = __floats2bfloat162_rn(s1[0], s1[1]);
                __nv_bfloat162 H3 = __floats2bfloat162_rn(s1[2], s1[3]);
                float2 g0 = __bfloat1622float2(H0);
                float2 g1 = __bfloat1622float2(H1);
                float2 g2 = __bfloat1622float2(H2);
                float2 g3 = __bfloat1622float2(H3);
                pha[0] = bits2(H0); pha[1] = bits2(H1);
                pha[2] = bits2(H2); pha[3] = bits2(H3);
                pla[0] = bits2(__floats2bfloat162_rn(s0[0]-g0.x, s0[1]-g0.y));
                pla[1] = bits2(__floats2bfloat162_rn(s0[2]-g1.x, s0[3]-g1.y));
                pla[2] = bits2(__floats2bfloat162_rn(s1[0]-g2.x, s1[1]-g2.y));
                pla[3] = bits2(__floats2bfloat162_rn(s1[2]-g3.x, s1[3]-g3.y));
            }
            const u32 vq = vbase + (u32)(16 * p * LDH * 2);
#pragma unroll
            for (int pr = 0; pr < 4; pr++) {
                const int nd0 = 2 * pr, nd1 = nd0 + 1;
                u32 vh[4], vl[4];
                u32 a = vq + (u32)((16 * pr) * 2);
                ldsm4t(a, vh);
                ldsm4t(a + MAT, vl);
                mma16816(o[nd0], pha, vh[0], vh[1]);
                mma16816(o[nd1], pha, vh[2], vh[3]);
                mma16816(o[nd0], pha, vl[0], vl[1]);
                mma16816(o[nd1], pha, vl[2], vl[3]);
                mma16816(o[nd0], pla, vh[0], vh[1]);
                mma16816(o[nd1], pla, vh[2], vh[3]);
            }
        }
    }

    // ---- reduce l across the 4-lane quad sharing each row ----
    l0 += __shfl_xor_sync(0xffffffffu, l0, 1);
    l0 += __shfl_xor_sync(0xffffffffu, l0, 2);
    l1 += __shfl_xor_sync(0xffffffffu, l1, 1);
    l1 += __shfl_xor_sync(0xffffffffu, l1, 2);
    const float inv0 = 1.0f / l0;
    const float inv1 = 1.0f / l1;

    // ---- write O ----
#pragma unroll
    for (int nd = 0; nd < 8; nd++) {
        int dcol = 8 * nd + 2 * (t & 3);
        *(float2*)&Oh[(size_t)m_r0 * D_ + dcol] =
            make_float2(o[nd][0] * inv0, o[nd][1] * inv0);
        *(float2*)&Oh[(size_t)m_r1 * D_ + dcol] =
            make_float2(o[nd][2] * inv1, o[nd][3] * inv1);
    }
}

extern "C" void kernel_launch(void* const* d_in, const int* in_sizes, int n_in,
                              void* d_out, int out_size)
{
    const float* q = (const float*)d_in[0];
    const float* k = (const float*)d_in[1];
    const float* v = (const float*)d_in[2];
    float* o = (float*)d_out;
    (void)in_sizes; (void)n_in; (void)out_size;

    prep_kernel<<<TOT4 / 256, 256>>>(k, v);

    cudaFuncSetAttribute(rbf_attn_mma,
                         cudaFuncAttributeMaxDynamicSharedMemorySize, SMEM_BYTES);

    dim3 grid(N_ / BM, 32);
    rbf_attn_mma<<<grid, NTH, SMEM_BYTES>>>(q, o);
}

// round 13
// speedup vs baseline: 1.2074x; 1.0123x over previous
#include <cuda_runtime.h>
#include <cuda_bf16.h>
#include <cstdint>

// RBF-kernel causal attention via warp-level mma.sync (bf16, hi/lo compensated).
// Round 13: R12 + per-warp critical-path cuts:
//  - QK: 4-way accumulator split (per-g chunk) -> MMA dep chain 12 -> 6 deep
//  - PV: ldsm ping-pong restored (prefetch next pr's V frags)
//  - softmax: ksq/qsq pre-scaled by -CEXP (in prep / at load); relu clamp
//    dropped (binds only on rounding noise for Gaussian data)
// B=2, H=16, N=2048, D=64. CTA: 64 queries, 4 warps, 64-key tiles.

#define N_   2048
#define D_   64
#define BM   64
#define BN   64
#define NTH  128
#define LDH  72                      // halves per bf16 smem row (144 B)
#define CEXP 0.18033688011112042f    // log2(e)/8

#define MAT    9216                  // 64 rows * 144 B
#define B_KH   0
#define B_KL   MAT
#define B_VH   (2*MAT)
#define B_VL   (3*MAT)
#define B_KSQ  (4*MAT)
#define BUF    (4*MAT + 256)         // 37120
#define OFF_QSQ (2*BUF)              // 74240
#define SMEM_BYTES (OFF_QSQ + 256)   // 74496

#define TOT4 (2*16*2048*16)          // float4 count per tensor

typedef uint32_t u32;

__device__ uint2 g_KH[TOT4];
__device__ uint2 g_KL[TOT4];
__device__ uint2 g_VH[TOT4];
__device__ uint2 g_VL[TOT4];
__device__ float g_ksq[2*16*2048];   // holds -CEXP * ||k||^2

__device__ __forceinline__ u32 smem_u32(const void* p) {
    u32 a;
    asm("{ .reg .u64 t; cvta.to.shared.u64 t, %1; cvt.u32.u64 %0, t; }"
        : "=r"(a) : "l"(p));
    return a;
}
__device__ __forceinline__ float ex2(float x) {
    float y; asm("ex2.approx.f32 %0, %1;" : "=f"(y) : "f"(x)); return y;
}
__device__ __forceinline__ void cp16(u32 saddr, const void* g) {
    asm volatile("cp.async.cg.shared.global [%0], [%1], 16;"
                 :: "r"(saddr), "l"(g) : "memory");
}
__device__ __forceinline__ void cp_commit() {
    asm volatile("cp.async.commit_group;" ::: "memory");
}
__device__ __forceinline__ void cp_wait0() {
    asm volatile("cp.async.wait_group 0;" ::: "memory");
}
__device__ __forceinline__ void ldsm4(u32 addr, u32 r[4]) {
    asm volatile("ldmatrix.sync.aligned.m8n8.x4.shared.b16 {%0,%1,%2,%3}, [%4];"
                 : "=r"(r[0]), "=r"(r[1]), "=r"(r[2]), "=r"(r[3]) : "r"(addr));
}
__device__ __forceinline__ void ldsm4t(u32 addr, u32 r[4]) {
    asm volatile("ldmatrix.sync.aligned.m8n8.x4.trans.shared.b16 {%0,%1,%2,%3}, [%4];"
                 : "=r"(r[0]), "=r"(r[1]), "=r"(r[2]), "=r"(r[3]) : "r"(addr));
}
__device__ __forceinline__ void mma16816(float d[4], const u32 a[4], u32 b0, u32 b1) {
    asm volatile(
        "mma.sync.aligned.m16n8k16.row.col.f32.bf16.bf16.f32 "
        "{%0,%1,%2,%3}, {%4,%5,%6,%7}, {%8,%9}, {%0,%1,%2,%3};"
        : "+f"(d[0]), "+f"(d[1]), "+f"(d[2]), "+f"(d[3])
        : "r"(a[0]), "r"(a[1]), "r"(a[2]), "r"(a[3]), "r"(b0), "r"(b1));
}
__device__ __forceinline__ u32 bits2(__nv_bfloat162 h) { return *(u32*)&h; }

__device__ __forceinline__ void split4(float4 v, uint2& hi, uint2& lo) {
    __nv_bfloat162 h0 = __floats2bfloat162_rn(v.x, v.y);
    __nv_bfloat162 h1 = __floats2bfloat162_rn(v.z, v.w);
    float2 f0 = __bfloat1622float2(h0);
    float2 f1 = __bfloat1622float2(h1);
    __nv_bfloat162 l0 = __floats2bfloat162_rn(v.x - f0.x, v.y - f0.y);
    __nv_bfloat162 l1 = __floats2bfloat162_rn(v.z - f1.x, v.w - f1.y);
    hi = make_uint2(bits2(h0), bits2(h1));
    lo = make_uint2(bits2(l0), bits2(l1));
}
__device__ __forceinline__ void cvt_store(char* smc, int off_hi, int off_lo, float4 v) {
    uint2 hi, lo;
    split4(v, hi, lo);
    *(uint2*)(smc + off_hi) = hi;
    *(uint2*)(smc + off_lo) = lo;
}

// ---------------- prep: f32 K/V -> bf16 hi/lo globals + scaled ksq ----------------
__global__ void __launch_bounds__(256)
prep_kernel(const float* __restrict__ K, const float* __restrict__ V)
{
    const int i = blockIdx.x * 256 + threadIdx.x;     // float4 index
    float4 k = ((const float4*)K)[i];
    float4 v = ((const float4*)V)[i];
    uint2 hi, lo;
    split4(k, hi, lo);
    g_KH[i] = hi; g_KL[i] = lo;
    split4(v, hi, lo);
    g_VH[i] = hi; g_VL[i] = lo;

    float s = fmaf(k.x, k.x, fmaf(k.y, k.y, fmaf(k.z, k.z, k.w * k.w)));
    s += __shfl_xor_sync(0xffffffffu, s, 1, 16);
    s += __shfl_xor_sync(0xffffffffu, s, 2, 16);
    s += __shfl_xor_sync(0xffffffffu, s, 4, 16);
    s += __shfl_xor_sync(0xffffffffu, s, 8, 16);
    if ((threadIdx.x & 15) == 0) g_ksq[i >> 4] = -CEXP * s;
}

// cp.async one full key-tile (KH,KL,VH,VL + ksq) into smem buffer at dst
__device__ __forceinline__ void cp_tile(u32 dst, size_t rowbase, int tid)
{
    const char* khg = (const char*)g_KH + rowbase * 128;
    const char* klg = (const char*)g_KL + rowbase * 128;
    const char* vhg = (const char*)g_VH + rowbase * 128;
    const char* vlg = (const char*)g_VL + rowbase * 128;
#pragma unroll
    for (int i = 0; i < 4; i++) {
        int c   = i * 128 + tid;        // 0..511
        int row = c >> 3;
        int c8  = c & 7;
        u32 so  = (u32)(row * 144 + c8 * 16);
        size_t go = (size_t)row * 128 + (size_t)c8 * 16;
        cp16(dst + B_KH + so, khg + go);
        cp16(dst + B_KL + so, klg + go);
        cp16(dst + B_VH + so, vhg + go);
        cp16(dst + B_VL + so, vlg + go);
    }
    if (tid < 16)
        cp16(dst + B_KSQ + (u32)(tid * 16), (const char*)(g_ksq + rowbase) + tid * 16);
}

// ---------------- main kernel ----------------
__global__ void __launch_bounds__(NTH, 3)
rbf_attn_mma(const float* __restrict__ Qg, float* __restrict__ Og)
{
    extern __shared__ char smc[];
    const u32 sb  = smem_u32(smc);
    const int tid = threadIdx.x;
    const int w   = tid >> 5;
    const int t   = tid & 31;
    const int bh  = blockIdx.y;
    const int qt  = (gridDim.x - 1) - blockIdx.x;    // heavy tiles first
    const int m0  = qt * BM;
    const int nkt = qt + 1;

    const float* Qh = Qg + (size_t)bh * N_ * D_;
    float*       Oh = Og + (size_t)bh * N_ * D_;

    // ---- prologue: cp tile 0 into buffer 0 ----
    cp_tile(sb, (size_t)bh * N_, tid);
    cp_commit();

    // ---- stage Q (hi/lo bf16) into buffer 1, compute qsq ----
    {
        const float4* Q4 = (const float4*)(Qh + (size_t)m0 * D_);
#pragma unroll
        for (int i = 0; i < 8; i++) {
            int fidx = i * NTH + tid;
            int row  = fidx >> 4;
            int c4   = (fidx & 15) << 2;
            cvt_store(smc, BUF + B_KH + (row * LDH + c4) * 2,
                           BUF + B_KL + (row * LDH + c4) * 2, Q4[fidx]);
        }
        if (tid < BM) {
            float s = 0.f;
            const float4* Qr = (const float4*)(Qh + (size_t)(m0 + tid) * D_);
#pragma unroll
            for (int j = 0; j < 16; j++) {
                float4 v = Qr[j];
                s = fmaf(v.x, v.x, fmaf(v.y, v.y, fmaf(v.z, v.z, fmaf(v.w, v.w, s))));
            }
            ((float*)(smc + OFF_QSQ))[tid] = s;
        }
    }
    __syncthreads();

    // ---- extract Q A-fragments (persist in regs across all tiles) ----
    u32 qa[4][4], ql[4][4];
    {
        const int row = w * 16 + (((t >> 3) & 1) << 3) + (t & 7);
        const int cg  = (t >> 4) << 3;
#pragma unroll
        for (int kc = 0; kc < 4; kc++) {
            u32 addr = sb + BUF + B_KH + (u32)((row * LDH + 16 * kc + cg) * 2);
            ldsm4(addr, qa[kc]);
            ldsm4(addr + MAT, ql[kc]);
        }
    }
    // pre-scaled: q0/q1 hold -CEXP * ||q||^2
    const float q0 = -CEXP * ((float*)(smc + OFF_QSQ))[w * 16 + (t >> 2)];
    const float q1 = -CEXP * ((float*)(smc + OFF_QSQ))[w * 16 + (t >> 2) + 8];
    const int m_r0 = m0 + w * 16 + (t >> 2);
    const int m_r1 = m_r0 + 8;

    float o[8][4];
#pragma unroll
    for (int i = 0; i < 8; i++)
#pragma unroll
        for (int j = 0; j < 4; j++) o[i][j] = 0.f;
    float l0 = 0.f, l1 = 0.f;

    for (int kt = 0; kt < nkt; kt++) {
        const int n0 = kt * BN;
        const u32 cb = sb + (u32)((kt & 1) * BUF);
        const char* cc = smc + (size_t)((kt & 1) * BUF);
        const bool diag = (kt == qt);

        cp_wait0();
        __syncthreads();

        if (kt + 1 < nkt)
            cp_tile(sb + (u32)(((kt + 1) & 1) * BUF),
                    (size_t)bh * N_ + (size_t)(n0 + BN), tid);
        cp_commit();

        // per-thread base addresses for this tile
        const u32 kbase = cb + (u32)((((t & 7)) * LDH + ((t >> 3) << 3)) * 2);
        const u32 vbase = cb + B_VH +
            (u32)(((((t >> 3) & 1) << 3) + (t & 7)) * LDH * 2 + (((t >> 4) << 3)) * 2);
        const float* ksq = (const float*)(cc + B_KSQ);   // -CEXP * ||k||^2

        // ==== 4 quarter-pipelined stages of 16 keys each ====
#pragma unroll
        for (int p = 0; p < 4; p++) {
            const int nb0 = 2 * p, nb1 = nb0 + 1;

            // ---- QK(p): 4-way accumulator split (per g chunk) ----
            float s0a[4] = {0.f, 0.f, 0.f, 0.f};
            float s1a[4] = {0.f, 0.f, 0.f, 0.f};
            float s0b[4] = {0.f, 0.f, 0.f, 0.f};
            float s1b[4] = {0.f, 0.f, 0.f, 0.f};
            {   // g = 0 -> s*a
                u32 a0 = kbase + (u32)((8 * nb0 * LDH) * 2);
                u32 a1 = a0 + (u32)(8 * LDH * 2);
                u32 kb0[4], kb1[4], kl0[4], kl1[4];
                ldsm4(a0, kb0);
                ldsm4(a1, kb1);
                ldsm4(a0 + MAT, kl0);
                ldsm4(a1 + MAT, kl1);
                mma16816(s0a, qa[0], kb0[0], kb0[1]);
                mma16816(s1a, qa[0], kb1[0], kb1[1]);
                mma16816(s0a, qa[1], kb0[2], kb0[3]);
                mma16816(s1a, qa[1], kb1[2], kb1[3]);
                mma16816(s0a, qa[0], kl0[0], kl0[1]);
                mma16816(s1a, qa[0], kl1[0], kl1[1]);
                mma16816(s0a, qa[1], kl0[2], kl0[3]);
                mma16816(s1a, qa[1], kl1[2], kl1[3]);
                mma16816(s0a, ql[0], kb0[0], kb0[1]);
                mma16816(s1a, ql[0], kb1[0], kb1[1]);
                mma16816(s0a, ql[1], kb0[2], kb0[3]);
                mma16816(s1a, ql[1], kb1[2], kb1[3]);
            }
            {   // g = 1 -> s*b (independent chains)
                u32 a0 = kbase + (u32)(((8 * nb0 * LDH) + 32) * 2);
                u32 a1 = a0 + (u32)(8 * LDH * 2);
                u32 kb0[4], kb1[4], kl0[4], kl1[4];
                ldsm4(a0, kb0);
                ldsm4(a1, kb1);
                ldsm4(a0 + MAT, kl0);
                ldsm4(a1 + MAT, kl1);
                mma16816(s0b, qa[2], kb0[0], kb0[1]);
                mma16816(s1b, qa[2], kb1[0], kb1[1]);
                mma16816(s0b, qa[3], kb0[2], kb0[3]);
                mma16816(s1b, qa[3], kb1[2], kb1[3]);
                mma16816(s0b, qa[2], kl0[0], kl0[1]);
                mma16816(s1b, qa[2], kl1[0], kl1[1]);
                mma16816(s0b, qa[3], kl0[2], kl0[3]);
                mma16816(s1b, qa[3], kl1[2], kl1[3]);
                mma16816(s0b, ql[2], kb0[0], kb0[1]);
                mma16816(s1b, ql[2], kb1[0], kb1[1]);
                mma16816(s0b, ql[3], kb0[2], kb0[3]);
                mma16816(s1b, ql[3], kb1[2], kb1[3]);
            }
            float s0[4], s1[4];
#pragma unroll
            for (int j = 0; j < 4; j++) {
                s0[j] = s0a[j] + s0b[j];
                s1[j] = s1a[j] + s1b[j];
            }

            // ---- softmax(p): p = ex2(2*CEXP*s + (q + kscaled)) ----
            {
                float2 kk0 = *(const float2*)&ksq[8 * nb0 + 2 * (t & 3)];
                float2 kk1 = *(const float2*)&ksq[8 * nb1 + 2 * (t & 3)];
                float p00 = ex2(fmaf(s0[0], 2.f*CEXP, q0 + kk0.x));
                float p01 = ex2(fmaf(s0[1], 2.f*CEXP, q0 + kk0.y));
                float p02 = ex2(fmaf(s0[2], 2.f*CEXP, q1 + kk0.x));
                float p03 = ex2(fmaf(s0[3], 2.f*CEXP, q1 + kk0.y));
                float p10 = ex2(fmaf(s1[0], 2.f*CEXP, q0 + kk1.x));
                float p11 = ex2(fmaf(s1[1], 2.f*CEXP, q0 + kk1.y));
                float p12 = ex2(fmaf(s1[2], 2.f*CEXP, q1 + kk1.x));
                float p13 = ex2(fmaf(s1[3], 2.f*CEXP, q1 + kk1.y));
                if (diag) {
                    int n0e = n0 + 8 * nb0 + 2 * (t & 3);
                    int n1e = n0 + 8 * nb1 + 2 * (t & 3);
                    if (n0e     > m_r0) p00 = 0.f;
                    if (n0e + 1 > m_r0) p01 = 0.f;
                    if (n0e     > m_r1) p02 = 0.f;
                    if (n0e + 1 > m_r1) p03 = 0.f;
                    if (n1e     > m_r0) p10 = 0.f;
                    if (n1e + 1 > m_r0) p11 = 0.f;
                    if (n1e     > m_r1) p12 = 0.f;
                    if (n1e + 1 > m_r1) p13 = 0.f;
                }
                l0 += (p00 + p01) + (p10 + p11);
                l1 += (p02 + p03) + (p12 + p13);
                s0[0] = p00; s0[1] = p01; s0[2] = p02; s0[3] = p03;
                s1[0] = p10; s1[1] = p11; s1[2] = p12; s1[3] = p13;
            }

            // ---- PV(p): cvt P, then prs with ldsm ping-pong ----
            u32 pha[4], pla[4];
            {
                __nv_bfloat162 H0 = __floats2bfloat162_rn(s0[0], s0[1]);
                __nv_bfloat162 H1 = __floats2bfloat162_rn(s0[2], s0[3]);
                __nv_bfloat162 H2 = __floats2bfloat162_rn(s1[0], s1[1]);
                __nv_bfloat162 H3 = __floats2bfloat162_rn(s1[2], s1[3]);
                float2 g0 = __bfloat1622float2(H0);
                float2 g1 = __bfloat1622float2(H1);
                float2 g2 = __bfloat1622float2(H2);
                float2 g3 = __bfloat1622float2(H3);
                pha[0] = bits2(H0); pha[1] = bits2(H1);
                pha[2] = bits2(H2); pha[3] = bits2(H3);
                pla[0] = bits2(__floats2bfloat162_rn(s0[0]-g0.x, s0[1]-g0.y));
                pla[1] = bits2(__floats2bfloat162_rn(s0[2]-g1.x, s0[3]-g1.y));
                pla[2] = bits2(__floats2bfloat162_rn(s1[0]-g2.x, s1[1]-g2.y));
                pla[3] = bits2(__floats2bfloat162_rn(s1[2]-g3.x, s1[3]-g3.y));
            }
            const u32 vq = vbase + (u32)(16 * p * LDH * 2);
            u32 vhp[2][4], vlp[2][4];
            ldsm4t(vq, vhp[0]);
            ldsm4t(vq + MAT, vlp[0]);
#pragma unroll
            for (int pr = 0; pr < 4; pr++) {
                const int cur = pr & 1;
                if (pr < 3) {
                    u32 an = vq + (u32)((16 * (pr + 1)) * 2);
                    ldsm4t(an, vhp[cur ^ 1]);
                    ldsm4t(an + MAT, vlp[cur ^ 1]);
                }
                const int nd0 = 2 * pr, nd1 = nd0 + 1;
                mma16816(o[nd0], pha, vhp[cur][0], vhp[cur][1]);
                mma16816(o[nd1], pha, vhp[cur][2], vhp[cur][3]);
                mma16816(o[nd0], pha, vlp[cur][0], vlp[cur][1]);
                mma16816(o[nd1], pha, vlp[cur][2], vlp[cur][3]);
                mma16816(o[nd0], pla, vhp[cur][0], vhp[cur][1]);
                mma16816(o[nd1], pla, vhp[cur][2], vhp[cur][3]);
            }
        }
    }

    // ---- reduce l across the 4-lane quad sharing each row ----
    l0 += __shfl_xor_sync(0xffffffffu, l0, 1);
    l0 += __shfl_xor_sync(0xffffffffu, l0, 2);
    l1 += __shfl_xor_sync(0xffffffffu, l1, 1);
    l1 += __shfl_xor_sync(0xffffffffu, l1, 2);
    const float inv0 = 1.0f / l0;
    const float inv1 = 1.0f / l1;

    // ---- write O ----
#pragma unroll
    for (int nd = 0; nd < 8; nd++) {
        int dcol = 8 * nd + 2 * (t & 3);
        *(float2*)&Oh[(size_t)m_r0 * D_ + dcol] =
            make_float2(o[nd][0] * inv0, o[nd][1] * inv0);
        *(float2*)&Oh[(size_t)m_r1 * D_ + dcol] =
            make_float2(o[nd][2] * inv1, o[nd][3] * inv1);
    }
}

extern "C" void kernel_launch(void* const* d_in, const int* in_sizes, int n_in,
                              void* d_out, int out_size)
{
    const float* q = (const float*)d_in[0];
    const float* k = (const float*)d_in[1];
    const float* v = (const float*)d_in[2];
    float* o = (float*)d_out;
    (void)in_sizes; (void)n_in; (void)out_size;

    prep_kernel<<<TOT4 / 256, 256>>>(k, v);

    cudaFuncSetAttribute(rbf_attn_mma,
                         cudaFuncAttributeMaxDynamicSharedMemorySize, SMEM_BYTES);

    dim3 grid(N_ / BM, 32);
    rbf_attn_mma<<<grid, NTH, SMEM_BYTES>>>(q, o);
}

// round 15
// speedup vs baseline: 1.2541x; 1.0387x over previous
#include <cuda_runtime.h>
#include <cuda_bf16.h>
#include <cuda_fp16.h>
#include <cstdint>

// RBF-kernel causal attention via warp-level mma.sync (hi/lo compensated).
// Round 15: online row-max rescaling (flash-style, log2 domain) makes fp16 P
// range-safe -> PV runs fp16: P single + V hi/lo (2 passes vs 3).
// QK unchanged (bf16, 3 passes, 4-way accumulator split).
// Masking folded into x = -2e30 (ex2 underflows to exact 0).
// B=2, H=16, N=2048, D=64. CTA: 64 queries, 4 warps, 64-key tiles.

#define N_   2048
#define D_   64
#define BM   64
#define BN   64
#define NTH  128
#define LDH  72                      // halves per b16 smem row (144 B)
#define CEXP 0.18033688011112042f    // log2(e)/8

#define MAT    9216                  // 64 rows * 144 B
#define B_KH   0
#define B_KL   MAT
#define B_VH   (2*MAT)
#define B_VL   (3*MAT)
#define B_KSQ  (4*MAT)
#define BUF    (4*MAT + 256)         // 37120
#define OFF_QSQ (2*BUF)              // 74240
#define SMEM_BYTES (OFF_QSQ + 256)   // 74496

#define TOT4 (2*16*2048*16)          // float4 count per tensor

typedef uint32_t u32;

__device__ uint2 g_KH[TOT4];         // bf16 hi
__device__ uint2 g_KL[TOT4];         // bf16 lo
__device__ uint2 g_VH[TOT4];         // fp16 hi
__device__ uint2 g_VL[TOT4];         // fp16 lo
__device__ float g_ksq[2*16*2048];   // holds -CEXP * ||k||^2

__device__ __forceinline__ u32 smem_u32(const void* p) {
    u32 a;
    asm("{ .reg .u64 t; cvta.to.shared.u64 t, %1; cvt.u32.u64 %0, t; }"
        : "=r"(a) : "l"(p));
    return a;
}
__device__ __forceinline__ float ex2(float x) {
    float y; asm("ex2.approx.f32 %0, %1;" : "=f"(y) : "f"(x)); return y;
}
__device__ __forceinline__ void cp16(u32 saddr, const void* g) {
    asm volatile("cp.async.cg.shared.global [%0], [%1], 16;"
                 :: "r"(saddr), "l"(g) : "memory");
}
__device__ __forceinline__ void cp_commit() {
    asm volatile("cp.async.commit_group;" ::: "memory");
}
__device__ __forceinline__ void cp_wait0() {
    asm volatile("cp.async.wait_group 0;" ::: "memory");
}
__device__ __forceinline__ void ldsm4(u32 addr, u32 r[4]) {
    asm volatile("ldmatrix.sync.aligned.m8n8.x4.shared.b16 {%0,%1,%2,%3}, [%4];"
                 : "=r"(r[0]), "=r"(r[1]), "=r"(r[2]), "=r"(r[3]) : "r"(addr));
}
__device__ __forceinline__ void ldsm4t(u32 addr, u32 r[4]) {
    asm volatile("ldmatrix.sync.aligned.m8n8.x4.trans.shared.b16 {%0,%1,%2,%3}, [%4];"
                 : "=r"(r[0]), "=r"(r[1]), "=r"(r[2]), "=r"(r[3]) : "r"(addr));
}
// bf16 MMA (QK^T)
__device__ __forceinline__ void mma_bf(float d[4], const u32 a[4], u32 b0, u32 b1) {
    asm volatile(
        "mma.sync.aligned.m16n8k16.row.col.f32.bf16.bf16.f32 "
        "{%0,%1,%2,%3}, {%4,%5,%6,%7}, {%8,%9}, {%0,%1,%2,%3};"
        : "+f"(d[0]), "+f"(d[1]), "+f"(d[2]), "+f"(d[3])
        : "r"(a[0]), "r"(a[1]), "r"(a[2]), "r"(a[3]), "r"(b0), "r"(b1));
}
// fp16 MMA (P.V)
__device__ __forceinline__ void mma_fp(float d[4], const u32 a[4], u32 b0, u32 b1) {
    asm volatile(
        "mma.sync.aligned.m16n8k16.row.col.f32.f16.f16.f32 "
        "{%0,%1,%2,%3}, {%4,%5,%6,%7}, {%8,%9}, {%0,%1,%2,%3};"
        : "+f"(d[0]), "+f"(d[1]), "+f"(d[2]), "+f"(d[3])
        : "r"(a[0]), "r"(a[1]), "r"(a[2]), "r"(a[3]), "r"(b0), "r"(b1));
}
__device__ __forceinline__ u32 bits2(__nv_bfloat162 h) { return *(u32*)&h; }
__device__ __forceinline__ u32 bits2h(__half2 h)       { return *(u32*)&h; }

__device__ __forceinline__ void split4_bf(float4 v, uint2& hi, uint2& lo) {
    __nv_bfloat162 h0 = __floats2bfloat162_rn(v.x, v.y);
    __nv_bfloat162 h1 = __floats2bfloat162_rn(v.z, v.w);
    float2 f0 = __bfloat1622float2(h0);
    float2 f1 = __bfloat1622float2(h1);
    __nv_bfloat162 l0 = __floats2bfloat162_rn(v.x - f0.x, v.y - f0.y);
    __nv_bfloat162 l1 = __floats2bfloat162_rn(v.z - f1.x, v.w - f1.y);
    hi = make_uint2(bits2(h0), bits2(h1));
    lo = make_uint2(bits2(l0), bits2(l1));
}
__device__ __forceinline__ void split4_fp(float4 v, uint2& hi, uint2& lo) {
    __half2 h0 = __floats2half2_rn(v.x, v.y);
    __half2 h1 = __floats2half2_rn(v.z, v.w);
    float2 f0 = __half22float2(h0);
    float2 f1 = __half22float2(h1);
    __half2 l0 = __floats2half2_rn(v.x - f0.x, v.y - f0.y);
    __half2 l1 = __floats2half2_rn(v.z - f1.x, v.w - f1.y);
    hi = make_uint2(bits2h(h0), bits2h(h1));
    lo = make_uint2(bits2h(l0), bits2h(l1));
}
__device__ __forceinline__ void cvt_store(char* smc, int off_hi, int off_lo, float4 v) {
    uint2 hi, lo;
    split4_bf(v, hi, lo);
    *(uint2*)(smc + off_hi) = hi;
    *(uint2*)(smc + off_lo) = lo;
}

// ---------------- prep: K -> bf16 hi/lo, V -> fp16 hi/lo, scaled ksq ----------------
__global__ void __launch_bounds__(256)
prep_kernel(const float* __restrict__ K, const float* __restrict__ V)
{
    const int i = blockIdx.x * 256 + threadIdx.x;     // float4 index
    float4 k = ((const float4*)K)[i];
    float4 v = ((const float4*)V)[i];
    uint2 hi, lo;
    split4_bf(k, hi, lo);
    g_KH[i] = hi; g_KL[i] = lo;
    split4_fp(v, hi, lo);
    g_VH[i] = hi; g_VL[i] = lo;

    float s = fmaf(k.x, k.x, fmaf(k.y, k.y, fmaf(k.z, k.z, k.w * k.w)));
    s += __shfl_xor_sync(0xffffffffu, s, 1, 16);
    s += __shfl_xor_sync(0xffffffffu, s, 2, 16);
    s += __shfl_xor_sync(0xffffffffu, s, 4, 16);
    s += __shfl_xor_sync(0xffffffffu, s, 8, 16);
    if ((threadIdx.x & 15) == 0) g_ksq[i >> 4] = -CEXP * s;
}

// cp.async one full key-tile (KH,KL,VH,VL + ksq) into smem buffer at dst
__device__ __forceinline__ void cp_tile(u32 dst, size_t rowbase, int tid)
{
    const char* khg = (const char*)g_KH + rowbase * 128;
    const char* klg = (const char*)g_KL + rowbase * 128;
    const char* vhg = (const char*)g_VH + rowbase * 128;
    const char* vlg = (const char*)g_VL + rowbase * 128;
#pragma unroll
    for (int i = 0; i < 4; i++) {
        int c   = i * 128 + tid;        // 0..511
        int row = c >> 3;
        int c8  = c & 7;
        u32 so  = (u32)(row * 144 + c8 * 16);
        size_t go = (size_t)row * 128 + (size_t)c8 * 16;
        cp16(dst + B_KH + so, khg + go);
        cp16(dst + B_KL + so, klg + go);
        cp16(dst + B_VH + so, vhg + go);
        cp16(dst + B_VL + so, vlg + go);
    }
    if (tid < 16)
        cp16(dst + B_KSQ + (u32)(tid * 16), (const char*)(g_ksq + rowbase) + tid * 16);
}

// ---------------- main kernel ----------------
__global__ void __launch_bounds__(NTH, 3)
rbf_attn_mma(const float* __restrict__ Qg, float* __restrict__ Og)
{
    extern __shared__ char smc[];
    const u32 sb  = smem_u32(smc);
    const int tid = threadIdx.x;
    const int w   = tid >> 5;
    const int t   = tid & 31;
    const int bh  = blockIdx.y;
    const int qt  = (gridDim.x - 1) - blockIdx.x;    // heavy tiles first
    const int m0  = qt * BM;
    const int nkt = qt + 1;

    const float* Qh = Qg + (size_t)bh * N_ * D_;
    float*       Oh = Og + (size_t)bh * N_ * D_;

    // ---- prologue: cp tile 0 into buffer 0 ----
    cp_tile(sb, (size_t)bh * N_, tid);
    cp_commit();

    // ---- stage Q (hi/lo bf16) into buffer 1, compute qsq ----
    {
        const float4* Q4 = (const float4*)(Qh + (size_t)m0 * D_);
#pragma unroll
        for (int i = 0; i < 8; i++) {
            int fidx = i * NTH + tid;
            int row  = fidx >> 4;
            int c4   = (fidx & 15) << 2;
            cvt_store(smc, BUF + B_KH + (row * LDH + c4) * 2,
                           BUF + B_KL + (row * LDH + c4) * 2, Q4[fidx]);
        }
        if (tid < BM) {
            float s = 0.f;
            const float4* Qr = (const float4*)(Qh + (size_t)(m0 + tid) * D_);
#pragma unroll
            for (int j = 0; j < 16; j++) {
                float4 v = Qr[j];
                s = fmaf(v.x, v.x, fmaf(v.y, v.y, fmaf(v.z, v.z, fmaf(v.w, v.w, s))));
            }
            ((float*)(smc + OFF_QSQ))[tid] = s;
        }
    }
    __syncthreads();

    // ---- extract Q A-fragments (persist in regs across all tiles) ----
    u32 qa[4][4], ql[4][4];
    {
        const int row = w * 16 + (((t >> 3) & 1) << 3) + (t & 7);
        const int cg  = (t >> 4) << 3;
#pragma unroll
        for (int kc = 0; kc < 4; kc++) {
            u32 addr = sb + BUF + B_KH + (u32)((row * LDH + 16 * kc + cg) * 2);
            ldsm4(addr, qa[kc]);
            ldsm4(addr + MAT, ql[kc]);
        }
    }
    // pre-scaled: q0/q1 hold -CEXP * ||q||^2
    const float q0 = -CEXP * ((float*)(smc + OFF_QSQ))[w * 16 + (t >> 2)];
    const float q1 = -CEXP * ((float*)(smc + OFF_QSQ))[w * 16 + (t >> 2) + 8];
    const int m_r0 = m0 + w * 16 + (t >> 2);
    const int m_r1 = m_r0 + 8;

    float o[8][4];
#pragma unroll
    for (int i = 0; i < 8; i++)
#pragma unroll
        for (int j = 0; j < 4; j++) o[i][j] = 0.f;
    float l0 = 0.f, l1 = 0.f;
    float M0 = -1e30f, M1 = -1e30f;    // running row max of log2-logits

    for (int kt = 0; kt < nkt; kt++) {
        const int n0 = kt * BN;
        const u32 cb = sb + (u32)((kt & 1) * BUF);
        const char* cc = smc + (size_t)((kt & 1) * BUF);
        const bool diag = (kt == qt);

        cp_wait0();
        __syncthreads();

        if (kt + 1 < nkt)
            cp_tile(sb + (u32)(((kt + 1) & 1) * BUF),
                    (size_t)bh * N_ + (size_t)(n0 + BN), tid);
        cp_commit();

        // per-thread base addresses for this tile
        const u32 kbase = cb + (u32)((((t & 7)) * LDH + ((t >> 3) << 3)) * 2);
        const u32 vbase = cb + B_VH +
            (u32)(((((t >> 3) & 1) << 3) + (t & 7)) * LDH * 2 + (((t >> 4) << 3)) * 2);
        const float* ksq = (const float*)(cc + B_KSQ);   // -CEXP * ||k||^2

        // ==== 4 quarter-pipelined stages of 16 keys each ====
#pragma unroll
        for (int p = 0; p < 4; p++) {
            const int nb0 = 2 * p, nb1 = nb0 + 1;

            // ---- QK(p): bf16, 3 passes, 4-way accumulator split ----
            float s0a[4] = {0.f, 0.f, 0.f, 0.f};
            float s1a[4] = {0.f, 0.f, 0.f, 0.f};
            float s0b[4] = {0.f, 0.f, 0.f, 0.f};
            float s1b[4] = {0.f, 0.f, 0.f, 0.f};
            {   // g = 0 -> s*a
                u32 a0 = kbase + (u32)((8 * nb0 * LDH) * 2);
                u32 a1 = a0 + (u32)(8 * LDH * 2);
                u32 kb0[4], kb1[4], kl0[4], kl1[4];
                ldsm4(a0, kb0);
                ldsm4(a1, kb1);
                ldsm4(a0 + MAT, kl0);
                ldsm4(a1 + MAT, kl1);
                mma_bf(s0a, qa[0], kb0[0], kb0[1]);
                mma_bf(s1a, qa[0], kb1[0], kb1[1]);
                mma_bf(s0a, qa[1], kb0[2], kb0[3]);
                mma_bf(s1a, qa[1], kb1[2], kb1[3]);
                mma_bf(s0a, qa[0], kl0[0], kl0[1]);
                mma_bf(s1a, qa[0], kl1[0], kl1[1]);
                mma_bf(s0a, qa[1], kl0[2], kl0[3]);
                mma_bf(s1a, qa[1], kl1[2], kl1[3]);
                mma_bf(s0a, ql[0], kb0[0], kb0[1]);
                mma_bf(s1a, ql[0], kb1[0], kb1[1]);
                mma_bf(s0a, ql[1], kb0[2], kb0[3]);
                mma_bf(s1a, ql[1], kb1[2], kb1[3]);
            }
            {   // g = 1 -> s*b (independent chains)
                u32 a0 = kbase + (u32)(((8 * nb0 * LDH) + 32) * 2);
                u32 a1 = a0 + (u32)(8 * LDH * 2);
                u32 kb0[4], kb1[4], kl0[4], kl1[4];
                ldsm4(a0, kb0);
                ldsm4(a1, kb1);
                ldsm4(a0 + MAT, kl0);
                ldsm4(a1 + MAT, kl1);
                mma_bf(s0b, qa[2], kb0[0], kb0[1]);
                mma_bf(s1b, qa[2], kb1[0], kb1[1]);
                mma_bf(s0b, qa[3], kb0[2], kb0[3]);
                mma_bf(s1b, qa[3], kb1[2], kb1[3]);
                mma_bf(s0b, qa[2], kl0[0], kl0[1]);
                mma_bf(s1b, qa[2], kl1[0], kl1[1]);
                mma_bf(s0b, qa[3], kl0[2], kl0[3]);
                mma_bf(s1b, qa[3], kl1[2], kl1[3]);
                mma_bf(s0b, ql[2], kb0[0], kb0[1]);
                mma_bf(s1b, ql[2], kb1[0], kb1[1]);
                mma_bf(s0b, ql[3], kb0[2], kb0[3]);
                mma_bf(s1b, ql[3], kb1[2], kb1[3]);
            }

            // ---- log2-logits x = 2*CEXP*s + (q + kscaled); mask -> -2e30 ----
            float2 kk0 = *(const float2*)&ksq[8 * nb0 + 2 * (t & 3)];
            float2 kk1 = *(const float2*)&ksq[8 * nb1 + 2 * (t & 3)];
            float x00 = fmaf(s0a[0] + s0b[0], 2.f*CEXP, q0 + kk0.x);
            float x01 = fmaf(s0a[1] + s0b[1], 2.f*CEXP, q0 + kk0.y);
            float x02 = fmaf(s0a[2] + s0b[2], 2.f*CEXP, q1 + kk0.x);
            float x03 = fmaf(s0a[3] + s0b[3], 2.f*CEXP, q1 + kk0.y);
            float x10 = fmaf(s1a[0] + s1b[0], 2.f*CEXP, q0 + kk1.x);
            float x11 = fmaf(s1a[1] + s1b[1], 2.f*CEXP, q0 + kk1.y);
            float x12 = fmaf(s1a[2] + s1b[2], 2.f*CEXP, q1 + kk1.x);
            float x13 = fmaf(s1a[3] + s1b[3], 2.f*CEXP, q1 + kk1.y);
            if (diag) {
                int n0e = n0 + 8 * nb0 + 2 * (t & 3);
                int n1e = n0 + 8 * nb1 + 2 * (t & 3);
                if (n0e     > m_r0) x00 = -2e30f;
                if (n0e + 1 > m_r0) x01 = -2e30f;
                if (n0e     > m_r1) x02 = -2e30f;
                if (n0e + 1 > m_r1) x03 = -2e30f;
                if (n1e     > m_r0) x10 = -2e30f;
                if (n1e + 1 > m_r0) x11 = -2e30f;
                if (n1e     > m_r1) x12 = -2e30f;
                if (n1e + 1 > m_r1) x13 = -2e30f;
            }

            // ---- online row max (quad-wide) + lazy rescale ----
            float qm0 = fmaxf(fmaxf(x00, x01), fmaxf(x10, x11));
            float qm1 = fmaxf(fmaxf(x02, x03), fmaxf(x12, x13));
            qm0 = fmaxf(qm0, __shfl_xor_sync(0xffffffffu, qm0, 1));
            qm0 = fmaxf(qm0, __shfl_xor_sync(0xffffffffu, qm0, 2));
            qm1 = fmaxf(qm1, __shfl_xor_sync(0xffffffffu, qm1, 1));
            qm1 = fmaxf(qm1, __shfl_xor_sync(0xffffffffu, qm1, 2));
            if (qm0 > M0) {
                float f = ex2(M0 - qm0);
                M0 = qm0;
                l0 *= f;
#pragma unroll
                for (int nd = 0; nd < 8; nd++) { o[nd][0] *= f; o[nd][1] *= f; }
            }
            if (qm1 > M1) {
                float f = ex2(M1 - qm1);
                M1 = qm1;
                l1 *= f;
#pragma unroll
                for (int nd = 0; nd < 8; nd++) { o[nd][2] *= f; o[nd][3] *= f; }
            }

            // ---- p = ex2(x - M); accumulate l; pack fp16 P fragment ----
            float p00 = ex2(x00 - M0), p01 = ex2(x01 - M0);
            float p02 = ex2(x02 - M1), p03 = ex2(x03 - M1);
            float p10 = ex2(x10 - M0), p11 = ex2(x11 - M0);
            float p12 = ex2(x12 - M1), p13 = ex2(x13 - M1);
            l0 += (p00 + p01) + (p10 + p11);
            l1 += (p02 + p03) + (p12 + p13);

            u32 pha[4];
            pha[0] = bits2h(__floats2half2_rn(p00, p01));
            pha[1] = bits2h(__floats2half2_rn(p02, p03));
            pha[2] = bits2h(__floats2half2_rn(p10, p11));
            pha[3] = bits2h(__floats2half2_rn(p12, p13));

            // ---- PV(p): fp16, P single + V hi/lo (2 passes), ldsm ping-pong ----
            const u32 vq = vbase + (u32)(16 * p * LDH * 2);
            u32 vhp[2][4], vlp[2][4];
            ldsm4t(vq, vhp[0]);
            ldsm4t(vq + MAT, vlp[0]);
#pragma unroll
            for (int pr = 0; pr < 4; pr++) {
                const int cur = pr & 1;
                if (pr < 3) {
                    u32 an = vq + (u32)((16 * (pr + 1)) * 2);
                    ldsm4t(an, vhp[cur ^ 1]);
                    ldsm4t(an + MAT, vlp[cur ^ 1]);
                }
                const int nd0 = 2 * pr, nd1 = nd0 + 1;
                mma_fp(o[nd0], pha, vhp[cur][0], vhp[cur][1]);
                mma_fp(o[nd1], pha, vhp[cur][2], vhp[cur][3]);
                mma_fp(o[nd0], pha, vlp[cur][0], vlp[cur][1]);
                mma_fp(o[nd1], pha, vlp[cur][2], vlp[cur][3]);
            }
        }
    }

    // ---- reduce l across the 4-lane quad sharing each row ----
    l0 += __shfl_xor_sync(0xffffffffu, l0, 1);
    l0 += __shfl_xor_sync(0xffffffffu, l0, 2);
    l1 += __shfl_xor_sync(0xffffffffu, l1, 1);
    l1 += __shfl_xor_sync(0xffffffffu, l1, 2);
    const float inv0 = 1.0f / l0;
    const float inv1 = 1.0f / l1;

    // ---- write O ----
#pragma unroll
    for (int nd = 0; nd < 8; nd++) {
        int dcol = 8 * nd + 2 * (t & 3);
        *(float2*)&Oh[(size_t)m_r0 * D_ + dcol] =
            make_float2(o[nd][0] * inv0, o[nd][1] * inv0);
        *(float2*)&Oh[(size_t)m_r1 * D_ + dcol] =
            make_float2(o[nd][2] * inv1, o[nd][3] * inv1);
    }
}

extern "C" void kernel_launch(void* const* d_in, const int* in_sizes, int n_in,
                              void* d_out, int out_size)
{
    const float* q = (const float*)d_in[0];
    const float* k = (const float*)d_in[1];
    const float* v = (const float*)d_in[2];
    float* o = (float*)d_out;
    (void)in_sizes; (void)n_in; (void)out_size;

    prep_kernel<<<TOT4 / 256, 256>>>(k, v);

    cudaFuncSetAttribute(rbf_attn_mma,
                         cudaFuncAttributeMaxDynamicSharedMemorySize, SMEM_BYTES);

    dim3 grid(N_ / BM, 32);
    rbf_attn_mma<<<grid, NTH, SMEM_BYTES>>>(q, o);
}

// round 16
// speedup vs baseline: 1.5415x; 1.2291x over previous
#include <cuda_runtime.h>
#include <cuda_bf16.h>
#include <cuda_fp16.h>
#include <cstdint>

// RBF-kernel causal attention via warp-level mma.sync (fp16, compensated).
// Round 16: QK re-precisioned to fp16 2-pass: K single fp16, Q fp16 hi/lo.
// (error budget: k-rounding -> s abs err ~1.1e-3 -> p rel err ~2.8e-4; online
// row-max from R15 keeps fp16 P range-safe.) PV: P single fp16 + V fp16 hi/lo.
// Total MMAs/tile 160 -> 128; K cp+ldsm traffic halves.
// B=2, H=16, N=2048, D=64. CTA: 64 queries, 4 warps, 64-key tiles.

#define N_   2048
#define D_   64
#define BM   64
#define BN   64
#define NTH  128
#define LDH  72                      // halves per b16 smem row (144 B)
#define CEXP 0.18033688011112042f    // log2(e)/8

#define MAT    9216                  // 64 rows * 144 B
#define B_K    0                     // fp16 K (single)
#define B_VH   MAT
#define B_VL   (2*MAT)
#define B_KSQ  (3*MAT)
#define BUF    (3*MAT + 256)         // 27904
#define OFF_QSQ (2*BUF)              // 55808
#define SMEM_BYTES (OFF_QSQ + 256)   // 56064

#define TOT4 (2*16*2048*16)          // float4 count per tensor

typedef uint32_t u32;

__device__ uint2 g_K [TOT4];         // fp16 (single)
__device__ uint2 g_VH[TOT4];         // fp16 hi
__device__ uint2 g_VL[TOT4];         // fp16 lo
__device__ float g_ksq[2*16*2048];   // holds -CEXP * ||k||^2 (exact fp32 k)

__device__ __forceinline__ u32 smem_u32(const void* p) {
    u32 a;
    asm("{ .reg .u64 t; cvta.to.shared.u64 t, %1; cvt.u32.u64 %0, t; }"
        : "=r"(a) : "l"(p));
    return a;
}
__device__ __forceinline__ float ex2(float x) {
    float y; asm("ex2.approx.f32 %0, %1;" : "=f"(y) : "f"(x)); return y;
}
__device__ __forceinline__ void cp16(u32 saddr, const void* g) {
    asm volatile("cp.async.cg.shared.global [%0], [%1], 16;"
                 :: "r"(saddr), "l"(g) : "memory");
}
__device__ __forceinline__ void cp_commit() {
    asm volatile("cp.async.commit_group;" ::: "memory");
}
__device__ __forceinline__ void cp_wait0() {
    asm volatile("cp.async.wait_group 0;" ::: "memory");
}
__device__ __forceinline__ void ldsm4(u32 addr, u32 r[4]) {
    asm volatile("ldmatrix.sync.aligned.m8n8.x4.shared.b16 {%0,%1,%2,%3}, [%4];"
                 : "=r"(r[0]), "=r"(r[1]), "=r"(r[2]), "=r"(r[3]) : "r"(addr));
}
__device__ __forceinline__ void ldsm4t(u32 addr, u32 r[4]) {
    asm volatile("ldmatrix.sync.aligned.m8n8.x4.trans.shared.b16 {%0,%1,%2,%3}, [%4];"
                 : "=r"(r[0]), "=r"(r[1]), "=r"(r[2]), "=r"(r[3]) : "r"(addr));
}
// fp16 MMA (both GEMMs)
__device__ __forceinline__ void mma_fp(float d[4], const u32 a[4], u32 b0, u32 b1) {
    asm volatile(
        "mma.sync.aligned.m16n8k16.row.col.f32.f16.f16.f32 "
        "{%0,%1,%2,%3}, {%4,%5,%6,%7}, {%8,%9}, {%0,%1,%2,%3};"
        : "+f"(d[0]), "+f"(d[1]), "+f"(d[2]), "+f"(d[3])
        : "r"(a[0]), "r"(a[1]), "r"(a[2]), "r"(a[3]), "r"(b0), "r"(b1));
}
__device__ __forceinline__ u32 bits2h(__half2 h) { return *(u32*)&h; }

__device__ __forceinline__ void split4_fp(float4 v, uint2& hi, uint2& lo) {
    __half2 h0 = __floats2half2_rn(v.x, v.y);
    __half2 h1 = __floats2half2_rn(v.z, v.w);
    float2 f0 = __half22float2(h0);
    float2 f1 = __half22float2(h1);
    __half2 l0 = __floats2half2_rn(v.x - f0.x, v.y - f0.y);
    __half2 l1 = __floats2half2_rn(v.z - f1.x, v.w - f1.y);
    hi = make_uint2(bits2h(h0), bits2h(h1));
    lo = make_uint2(bits2h(l0), bits2h(l1));
}

// ---------------- prep: K -> fp16 single, V -> fp16 hi/lo, scaled ksq ----------------
__global__ void __launch_bounds__(256)
prep_kernel(const float* __restrict__ K, const float* __restrict__ V)
{
    const int i = blockIdx.x * 256 + threadIdx.x;     // float4 index
    float4 k = ((const float4*)K)[i];
    float4 v = ((const float4*)V)[i];
    uint2 hi, lo;
    split4_fp(k, hi, lo);
    g_K[i] = hi;                       // single-precision fp16 K
    split4_fp(v, hi, lo);
    g_VH[i] = hi; g_VL[i] = lo;

    float s = fmaf(k.x, k.x, fmaf(k.y, k.y, fmaf(k.z, k.z, k.w * k.w)));
    s += __shfl_xor_sync(0xffffffffu, s, 1, 16);
    s += __shfl_xor_sync(0xffffffffu, s, 2, 16);
    s += __shfl_xor_sync(0xffffffffu, s, 4, 16);
    s += __shfl_xor_sync(0xffffffffu, s, 8, 16);
    if ((threadIdx.x & 15) == 0) g_ksq[i >> 4] = -CEXP * s;
}

// cp.async one full key-tile (K,VH,VL + ksq) into smem buffer at dst
__device__ __forceinline__ void cp_tile(u32 dst, size_t rowbase, int tid)
{
    const char* kg  = (const char*)g_K  + rowbase * 128;
    const char* vhg = (const char*)g_VH + rowbase * 128;
    const char* vlg = (const char*)g_VL + rowbase * 128;
#pragma unroll
    for (int i = 0; i < 4; i++) {
        int c   = i * 128 + tid;        // 0..511
        int row = c >> 3;
        int c8  = c & 7;
        u32 so  = (u32)(row * 144 + c8 * 16);
        size_t go = (size_t)row * 128 + (size_t)c8 * 16;
        cp16(dst + B_K  + so, kg  + go);
        cp16(dst + B_VH + so, vhg + go);
        cp16(dst + B_VL + so, vlg + go);
    }
    if (tid < 16)
        cp16(dst + B_KSQ + (u32)(tid * 16), (const char*)(g_ksq + rowbase) + tid * 16);
}

// ---------------- main kernel ----------------
__global__ void __launch_bounds__(NTH, 3)
rbf_attn_mma(const float* __restrict__ Qg, float* __restrict__ Og)
{
    extern __shared__ char smc[];
    const u32 sb  = smem_u32(smc);
    const int tid = threadIdx.x;
    const int w   = tid >> 5;
    const int t   = tid & 31;
    const int bh  = blockIdx.y;
    const int qt  = (gridDim.x - 1) - blockIdx.x;    // heavy tiles first
    const int m0  = qt * BM;
    const int nkt = qt + 1;

    const float* Qh = Qg + (size_t)bh * N_ * D_;
    float*       Oh = Og + (size_t)bh * N_ * D_;

    // ---- prologue: cp tile 0 into buffer 0 ----
    cp_tile(sb, (size_t)bh * N_, tid);
    cp_commit();

    // ---- stage Q (hi/lo fp16) into buffer 1, compute qsq ----
    {
        const float4* Q4 = (const float4*)(Qh + (size_t)m0 * D_);
#pragma unroll
        for (int i = 0; i < 8; i++) {
            int fidx = i * NTH + tid;
            int row  = fidx >> 4;
            int c4   = (fidx & 15) << 2;
            uint2 hi, lo;
            split4_fp(Q4[fidx], hi, lo);
            *(uint2*)(smc + BUF + (row * LDH + c4) * 2)       = hi;
            *(uint2*)(smc + BUF + MAT + (row * LDH + c4) * 2) = lo;
        }
        if (tid < BM) {
            float s = 0.f;
            const float4* Qr = (const float4*)(Qh + (size_t)(m0 + tid) * D_);
#pragma unroll
            for (int j = 0; j < 16; j++) {
                float4 v = Qr[j];
                s = fmaf(v.x, v.x, fmaf(v.y, v.y, fmaf(v.z, v.z, fmaf(v.w, v.w, s))));
            }
            ((float*)(smc + OFF_QSQ))[tid] = s;
        }
    }
    __syncthreads();

    // ---- extract Q A-fragments (persist in regs across all tiles) ----
    u32 qa[4][4], ql[4][4];
    {
        const int row = w * 16 + (((t >> 3) & 1) << 3) + (t & 7);
        const int cg  = (t >> 4) << 3;
#pragma unroll
        for (int kc = 0; kc < 4; kc++) {
            u32 addr = sb + BUF + (u32)((row * LDH + 16 * kc + cg) * 2);
            ldsm4(addr, qa[kc]);
            ldsm4(addr + MAT, ql[kc]);
        }
    }
    // pre-scaled: q0/q1 hold -CEXP * ||q||^2
    const float q0 = -CEXP * ((float*)(smc + OFF_QSQ))[w * 16 + (t >> 2)];
    const float q1 = -CEXP * ((float*)(smc + OFF_QSQ))[w * 16 + (t >> 2) + 8];
    const int m_r0 = m0 + w * 16 + (t >> 2);
    const int m_r1 = m_r0 + 8;

    float o[8][4];
#pragma unroll
    for (int i = 0; i < 8; i++)
#pragma unroll
        for (int j = 0; j < 4; j++) o[i][j] = 0.f;
    float l0 = 0.f, l1 = 0.f;
    float M0 = -1e30f, M1 = -1e30f;    // running row max of log2-logits

    for (int kt = 0; kt < nkt; kt++) {
        const int n0 = kt * BN;
        const u32 cb = sb + (u32)((kt & 1) * BUF);
        const char* cc = smc + (size_t)((kt & 1) * BUF);
        const bool diag = (kt == qt);

        cp_wait0();
        __syncthreads();

        if (kt + 1 < nkt)
            cp_tile(sb + (u32)(((kt + 1) & 1) * BUF),
                    (size_t)bh * N_ + (size_t)(n0 + BN), tid);
        cp_commit();

        // per-thread base addresses for this tile
        const u32 kbase = cb + (u32)((((t & 7)) * LDH + ((t >> 3) << 3)) * 2);
        const u32 vbase = cb + B_VH +
            (u32)(((((t >> 3) & 1) << 3) + (t & 7)) * LDH * 2 + (((t >> 4) << 3)) * 2);
        const float* ksq = (const float*)(cc + B_KSQ);   // -CEXP * ||k||^2

        // ==== 4 quarter-pipelined stages of 16 keys each ====
#pragma unroll
        for (int p = 0; p < 4; p++) {
            const int nb0 = 2 * p, nb1 = nb0 + 1;

            // ---- QK(p): fp16, 2 passes (qh.k + ql.k), 4-way acc split ----
            float s0a[4] = {0.f, 0.f, 0.f, 0.f};
            float s1a[4] = {0.f, 0.f, 0.f, 0.f};
            float s0b[4] = {0.f, 0.f, 0.f, 0.f};
            float s1b[4] = {0.f, 0.f, 0.f, 0.f};
            {   // g = 0 -> s*a
                u32 a0 = kbase + (u32)((8 * nb0 * LDH) * 2);
                u32 a1 = a0 + (u32)(8 * LDH * 2);
                u32 kb0[4], kb1[4];
                ldsm4(a0, kb0);
                ldsm4(a1, kb1);
                mma_fp(s0a, qa[0], kb0[0], kb0[1]);
                mma_fp(s1a, qa[0], kb1[0], kb1[1]);
                mma_fp(s0a, qa[1], kb0[2], kb0[3]);
                mma_fp(s1a, qa[1], kb1[2], kb1[3]);
                mma_fp(s0a, ql[0], kb0[0], kb0[1]);
                mma_fp(s1a, ql[0], kb1[0], kb1[1]);
                mma_fp(s0a, ql[1], kb0[2], kb0[3]);
                mma_fp(s1a, ql[1], kb1[2], kb1[3]);
            }
            {   // g = 1 -> s*b (independent chains)
                u32 a0 = kbase + (u32)(((8 * nb0 * LDH) + 32) * 2);
                u32 a1 = a0 + (u32)(8 * LDH * 2);
                u32 kb0[4], kb1[4];
                ldsm4(a0, kb0);
                ldsm4(a1, kb1);
                mma_fp(s0b, qa[2], kb0[0], kb0[1]);
                mma_fp(s1b, qa[2], kb1[0], kb1[1]);
                mma_fp(s0b, qa[3], kb0[2], kb0[3]);
                mma_fp(s1b, qa[3], kb1[2], kb1[3]);
                mma_fp(s0b, ql[2], kb0[0], kb0[1]);
                mma_fp(s1b, ql[2], kb1[0], kb1[1]);
                mma_fp(s0b, ql[3], kb0[2], kb0[3]);
                mma_fp(s1b, ql[3], kb1[2], kb1[3]);
            }

            // ---- log2-logits x = 2*CEXP*s + (q + kscaled); mask -> -2e30 ----
            float2 kk0 = *(const float2*)&ksq[8 * nb0 + 2 * (t & 3)];
            float2 kk1 = *(const float2*)&ksq[8 * nb1 + 2 * (t & 3)];
            float x00 = fmaf(s0a[0] + s0b[0], 2.f*CEXP, q0 + kk0.x);
            float x01 = fmaf(s0a[1] + s0b[1], 2.f*CEXP, q0 + kk0.y);
            float x02 = fmaf(s0a[2] + s0b[2], 2.f*CEXP, q1 + kk0.x);
            float x03 = fmaf(s0a[3] + s0b[3], 2.f*CEXP, q1 + kk0.y);
            float x10 = fmaf(s1a[0] + s1b[0], 2.f*CEXP, q0 + kk1.x);
            float x11 = fmaf(s1a[1] + s1b[1], 2.f*CEXP, q0 + kk1.y);
            float x12 = fmaf(s1a[2] + s1b[2], 2.f*CEXP, q1 + kk1.x);
            float x13 = fmaf(s1a[3] + s1b[3], 2.f*CEXP, q1 + kk1.y);
            if (diag) {
                int n0e = n0 + 8 * nb0 + 2 * (t & 3);
                int n1e = n0 + 8 * nb1 + 2 * (t & 3);
                if (n0e     > m_r0) x00 = -2e30f;
                if (n0e + 1 > m_r0) x01 = -2e30f;
                if (n0e     > m_r1) x02 = -2e30f;
                if (n0e + 1 > m_r1) x03 = -2e30f;
                if (n1e     > m_r0) x10 = -2e30f;
                if (n1e + 1 > m_r0) x11 = -2e30f;
                if (n1e     > m_r1) x12 = -2e30f;
                if (n1e + 1 > m_r1) x13 = -2e30f;
            }

            // ---- online row max (quad-wide) + lazy rescale ----
            float qm0 = fmaxf(fmaxf(x00, x01), fmaxf(x10, x11));
            float qm1 = fmaxf(fmaxf(x02, x03), fmaxf(x12, x13));
            qm0 = fmaxf(qm0, __shfl_xor_sync(0xffffffffu, qm0, 1));
            qm0 = fmaxf(qm0, __shfl_xor_sync(0xffffffffu, qm0, 2));
            qm1 = fmaxf(qm1, __shfl_xor_sync(0xffffffffu, qm1, 1));
            qm1 = fmaxf(qm1, __shfl_xor_sync(0xffffffffu, qm1, 2));
            if (qm0 > M0) {
                float f = ex2(M0 - qm0);
                M0 = qm0;
                l0 *= f;
#pragma unroll
                for (int nd = 0; nd < 8; nd++) { o[nd][0] *= f; o[nd][1] *= f; }
            }
            if (qm1 > M1) {
                float f = ex2(M1 - qm1);
                M1 = qm1;
                l1 *= f;
#pragma unroll
                for (int nd = 0; nd < 8; nd++) { o[nd][2] *= f; o[nd][3] *= f; }
            }

            // ---- p = ex2(x - M); accumulate l; pack fp16 P fragment ----
            float p00 = ex2(x00 - M0), p01 = ex2(x01 - M0);
            float p02 = ex2(x02 - M1), p03 = ex2(x03 - M1);
            float p10 = ex2(x10 - M0), p11 = ex2(x11 - M0);
            float p12 = ex2(x12 - M1), p13 = ex2(x13 - M1);
            l0 += (p00 + p01) + (p10 + p11);
            l1 += (p02 + p03) + (p12 + p13);

            u32 pha[4];
            pha[0] = bits2h(__floats2half2_rn(p00, p01));
            pha[1] = bits2h(__floats2half2_rn(p02, p03));
            pha[2] = bits2h(__floats2half2_rn(p10, p11));
            pha[3] = bits2h(__floats2half2_rn(p12, p13));

            // ---- PV(p): fp16, P single + V hi/lo (2 passes), ldsm ping-pong ----
            const u32 vq = vbase + (u32)(16 * p * LDH * 2);
            u32 vhp[2][4], vlp[2][4];
            ldsm4t(vq, vhp[0]);
            ldsm4t(vq + MAT, vlp[0]);
#pragma unroll
            for (int pr = 0; pr < 4; pr++) {
                const int cur = pr & 1;
                if (pr < 3) {
                    u32 an = vq + (u32)((16 * (pr + 1)) * 2);
                    ldsm4t(an, vhp[cur ^ 1]);
                    ldsm4t(an + MAT, vlp[cur ^ 1]);
                }
                const int nd0 = 2 * pr, nd1 = nd0 + 1;
                mma_fp(o[nd0], pha, vhp[cur][0], vhp[cur][1]);
                mma_fp(o[nd1], pha, vhp[cur][2], vhp[cur][3]);
                mma_fp(o[nd0], pha, vlp[cur][0], vlp[cur][1]);
                mma_fp(o[nd1], pha, vlp[cur][2], vlp[cur][3]);
            }
        }
    }

    // ---- reduce l across the 4-lane quad sharing each row ----
    l0 += __shfl_xor_sync(0xffffffffu, l0, 1);
    l0 += __shfl_xor_sync(0xffffffffu, l0, 2);
    l1 += __shfl_xor_sync(0xffffffffu, l1, 1);
    l1 += __shfl_xor_sync(0xffffffffu, l1, 2);
    const float inv0 = 1.0f / l0;
    const float inv1 = 1.0f / l1;

    // ---- write O ----
#pragma unroll
    for (int nd = 0; nd < 8; nd++) {
        int dcol = 8 * nd + 2 * (t & 3);
        *(float2*)&Oh[(size_t)m_r0 * D_ + dcol] =
            make_float2(o[nd][0] * inv0, o[nd][1] * inv0);
        *(float2*)&Oh[(size_t)m_r1 * D_ + dcol] =
            make_float2(o[nd][2] * inv1, o[nd][3] * inv1);
    }
}

extern "C" void kernel_launch(void* const* d_in, const int* in_sizes, int n_in,
                              void* d_out, int out_size)
{
    const float* q = (const float*)d_in[0];
    const float* k = (const float*)d_in[1];
    const float* v = (const float*)d_in[2];
    float* o = (float*)d_out;
    (void)in_sizes; (void)n_in; (void)out_size;

    prep_kernel<<<TOT4 / 256, 256>>>(k, v);

    cudaFuncSetAttribute(rbf_attn_mma,
                         cudaFuncAttributeMaxDynamicSharedMemorySize, SMEM_BYTES);

    dim3 grid(N_ / BM, 32);
    rbf_attn_mma<<<grid, NTH, SMEM_BYTES>>>(q, o);
}

// round 17
// speedup vs baseline: 1.8681x; 1.2118x over previous
#include <cuda_runtime.h>
#include <cuda_bf16.h>
#include <cuda_fp16.h>
#include <cstdint>

// RBF-kernel causal attention via warp-level mma.sync (fp16, compensated).
// Round 17: V single fp16 (drop V-lo pass): PV = 1 pass. QK = 2 passes
// (K single fp16, Q fp16 hi/lo). Online row-max keeps P range-safe.
// Total MMAs/tile 128 -> 96; VL cp stream + half of PV ldsm removed.
// Error budget: measured 3.44e-4 (R16) + V rounding ~1.4e-4 -> ~3.7e-4.
// B=2, H=16, N=2048, D=64. CTA: 64 queries, 4 warps, 64-key tiles.

#define N_   2048
#define D_   64
#define BM   64
#define BN   64
#define NTH  128
#define LDH  72                      // halves per b16 smem row (144 B)
#define CEXP 0.18033688011112042f    // log2(e)/8

#define MAT    9216                  // 64 rows * 144 B
#define B_K    0                     // fp16 K (single)
#define B_V    MAT                   // fp16 V (single)
#define B_KSQ  (2*MAT)
#define BUF    (2*MAT + 256)         // 18688
#define OFF_QSQ (2*BUF)              // 37376
#define SMEM_BYTES (OFF_QSQ + 256)   // 37632

#define TOT4 (2*16*2048*16)          // float4 count per tensor

typedef uint32_t u32;

__device__ uint2 g_K [TOT4];         // fp16 (single)
__device__ uint2 g_V [TOT4];         // fp16 (single)
__device__ float g_ksq[2*16*2048];   // holds -CEXP * ||k||^2 (exact fp32 k)

__device__ __forceinline__ u32 smem_u32(const void* p) {
    u32 a;
    asm("{ .reg .u64 t; cvta.to.shared.u64 t, %1; cvt.u32.u64 %0, t; }"
        : "=r"(a) : "l"(p));
    return a;
}
__device__ __forceinline__ float ex2(float x) {
    float y; asm("ex2.approx.f32 %0, %1;" : "=f"(y) : "f"(x)); return y;
}
__device__ __forceinline__ void cp16(u32 saddr, const void* g) {
    asm volatile("cp.async.cg.shared.global [%0], [%1], 16;"
                 :: "r"(saddr), "l"(g) : "memory");
}
__device__ __forceinline__ void cp_commit() {
    asm volatile("cp.async.commit_group;" ::: "memory");
}
__device__ __forceinline__ void cp_wait0() {
    asm volatile("cp.async.wait_group 0;" ::: "memory");
}
__device__ __forceinline__ void ldsm4(u32 addr, u32 r[4]) {
    asm volatile("ldmatrix.sync.aligned.m8n8.x4.shared.b16 {%0,%1,%2,%3}, [%4];"
                 : "=r"(r[0]), "=r"(r[1]), "=r"(r[2]), "=r"(r[3]) : "r"(addr));
}
__device__ __forceinline__ void ldsm4t(u32 addr, u32 r[4]) {
    asm volatile("ldmatrix.sync.aligned.m8n8.x4.trans.shared.b16 {%0,%1,%2,%3}, [%4];"
                 : "=r"(r[0]), "=r"(r[1]), "=r"(r[2]), "=r"(r[3]) : "r"(addr));
}
// fp16 MMA (both GEMMs)
__device__ __forceinline__ void mma_fp(float d[4], const u32 a[4], u32 b0, u32 b1) {
    asm volatile(
        "mma.sync.aligned.m16n8k16.row.col.f32.f16.f16.f32 "
        "{%0,%1,%2,%3}, {%4,%5,%6,%7}, {%8,%9}, {%0,%1,%2,%3};"
        : "+f"(d[0]), "+f"(d[1]), "+f"(d[2]), "+f"(d[3])
        : "r"(a[0]), "r"(a[1]), "r"(a[2]), "r"(a[3]), "r"(b0), "r"(b1));
}
__device__ __forceinline__ u32 bits2h(__half2 h) { return *(u32*)&h; }

__device__ __forceinline__ void split4_fp(float4 v, uint2& hi, uint2& lo) {
    __half2 h0 = __floats2half2_rn(v.x, v.y);
    __half2 h1 = __floats2half2_rn(v.z, v.w);
    float2 f0 = __half22float2(h0);
    float2 f1 = __half22float2(h1);
    __half2 l0 = __floats2half2_rn(v.x - f0.x, v.y - f0.y);
    __half2 l1 = __floats2half2_rn(v.z - f1.x, v.w - f1.y);
    hi = make_uint2(bits2h(h0), bits2h(h1));
    lo = make_uint2(bits2h(l0), bits2h(l1));
}
__device__ __forceinline__ uint2 cvt4_fp(float4 v) {
    __half2 h0 = __floats2half2_rn(v.x, v.y);
    __half2 h1 = __floats2half2_rn(v.z, v.w);
    return make_uint2(bits2h(h0), bits2h(h1));
}

// ---------------- prep: K,V -> fp16 single, scaled ksq ----------------
__global__ void __launch_bounds__(256)
prep_kernel(const float* __restrict__ K, const float* __restrict__ V)
{
    const int i = blockIdx.x * 256 + threadIdx.x;     // float4 index
    float4 k = ((const float4*)K)[i];
    float4 v = ((const float4*)V)[i];
    g_K[i] = cvt4_fp(k);
    g_V[i] = cvt4_fp(v);

    float s = fmaf(k.x, k.x, fmaf(k.y, k.y, fmaf(k.z, k.z, k.w * k.w)));
    s += __shfl_xor_sync(0xffffffffu, s, 1, 16);
    s += __shfl_xor_sync(0xffffffffu, s, 2, 16);
    s += __shfl_xor_sync(0xffffffffu, s, 4, 16);
    s += __shfl_xor_sync(0xffffffffu, s, 8, 16);
    if ((threadIdx.x & 15) == 0) g_ksq[i >> 4] = -CEXP * s;
}

// cp.async one full key-tile (K,V + ksq) into smem buffer at dst
__device__ __forceinline__ void cp_tile(u32 dst, size_t rowbase, int tid)
{
    const char* kg = (const char*)g_K + rowbase * 128;
    const char* vg = (const char*)g_V + rowbase * 128;
#pragma unroll
    for (int i = 0; i < 4; i++) {
        int c   = i * 128 + tid;        // 0..511
        int row = c >> 3;
        int c8  = c & 7;
        u32 so  = (u32)(row * 144 + c8 * 16);
        size_t go = (size_t)row * 128 + (size_t)c8 * 16;
        cp16(dst + B_K + so, kg + go);
        cp16(dst + B_V + so, vg + go);
    }
    if (tid < 16)
        cp16(dst + B_KSQ + (u32)(tid * 16), (const char*)(g_ksq + rowbase) + tid * 16);
}

// ---------------- main kernel ----------------
__global__ void __launch_bounds__(NTH, 3)
rbf_attn_mma(const float* __restrict__ Qg, float* __restrict__ Og)
{
    extern __shared__ char smc[];
    const u32 sb  = smem_u32(smc);
    const int tid = threadIdx.x;
    const int w   = tid >> 5;
    const int t   = tid & 31;
    const int bh  = blockIdx.y;
    const int qt  = (gridDim.x - 1) - blockIdx.x;    // heavy tiles first
    const int m0  = qt * BM;
    const int nkt = qt + 1;

    const float* Qh = Qg + (size_t)bh * N_ * D_;
    float*       Oh = Og + (size_t)bh * N_ * D_;

    // ---- prologue: cp tile 0 into buffer 0 ----
    cp_tile(sb, (size_t)bh * N_, tid);
    cp_commit();

    // ---- stage Q (hi/lo fp16) into buffer 1, compute qsq ----
    {
        const float4* Q4 = (const float4*)(Qh + (size_t)m0 * D_);
#pragma unroll
        for (int i = 0; i < 8; i++) {
            int fidx = i * NTH + tid;
            int row  = fidx >> 4;
            int c4   = (fidx & 15) << 2;
            uint2 hi, lo;
            split4_fp(Q4[fidx], hi, lo);
            *(uint2*)(smc + BUF + (row * LDH + c4) * 2)       = hi;
            *(uint2*)(smc + BUF + MAT + (row * LDH + c4) * 2) = lo;
        }
        if (tid < BM) {
            float s = 0.f;
            const float4* Qr = (const float4*)(Qh + (size_t)(m0 + tid) * D_);
#pragma unroll
            for (int j = 0; j < 16; j++) {
                float4 v = Qr[j];
                s = fmaf(v.x, v.x, fmaf(v.y, v.y, fmaf(v.z, v.z, fmaf(v.w, v.w, s))));
            }
            ((float*)(smc + OFF_QSQ))[tid] = s;
        }
    }
    __syncthreads();

    // ---- extract Q A-fragments (persist in regs across all tiles) ----
    u32 qa[4][4], ql[4][4];
    {
        const int row = w * 16 + (((t >> 3) & 1) << 3) + (t & 7);
        const int cg  = (t >> 4) << 3;
#pragma unroll
        for (int kc = 0; kc < 4; kc++) {
            u32 addr = sb + BUF + (u32)((row * LDH + 16 * kc + cg) * 2);
            ldsm4(addr, qa[kc]);
            ldsm4(addr + MAT, ql[kc]);
        }
    }
    // pre-scaled: q0/q1 hold -CEXP * ||q||^2
    const float q0 = -CEXP * ((float*)(smc + OFF_QSQ))[w * 16 + (t >> 2)];
    const float q1 = -CEXP * ((float*)(smc + OFF_QSQ))[w * 16 + (t >> 2) + 8];
    const int m_r0 = m0 + w * 16 + (t >> 2);
    const int m_r1 = m_r0 + 8;

    float o[8][4];
#pragma unroll
    for (int i = 0; i < 8; i++)
#pragma unroll
        for (int j = 0; j < 4; j++) o[i][j] = 0.f;
    float l0 = 0.f, l1 = 0.f;
    float M0 = -1e30f, M1 = -1e30f;    // running row max of log2-logits

    for (int kt = 0; kt < nkt; kt++) {
        const int n0 = kt * BN;
        const u32 cb = sb + (u32)((kt & 1) * BUF);
        const char* cc = smc + (size_t)((kt & 1) * BUF);
        const bool diag = (kt == qt);

        cp_wait0();
        __syncthreads();

        if (kt + 1 < nkt)
            cp_tile(sb + (u32)(((kt + 1) & 1) * BUF),
                    (size_t)bh * N_ + (size_t)(n0 + BN), tid);
        cp_commit();

        // per-thread base addresses for this tile
        const u32 kbase = cb + (u32)((((t & 7)) * LDH + ((t >> 3) << 3)) * 2);
        const u32 vbase = cb + B_V +
            (u32)(((((t >> 3) & 1) << 3) + (t & 7)) * LDH * 2 + (((t >> 4) << 3)) * 2);
        const float* ksq = (const float*)(cc + B_KSQ);   // -CEXP * ||k||^2

        // ==== 4 quarter-pipelined stages of 16 keys each ====
#pragma unroll
        for (int p = 0; p < 4; p++) {
            const int nb0 = 2 * p, nb1 = nb0 + 1;

            // ---- QK(p): fp16, 2 passes (qh.k + ql.k), 4-way acc split ----
            float s0a[4] = {0.f, 0.f, 0.f, 0.f};
            float s1a[4] = {0.f, 0.f, 0.f, 0.f};
            float s0b[4] = {0.f, 0.f, 0.f, 0.f};
            float s1b[4] = {0.f, 0.f, 0.f, 0.f};
            {   // g = 0 -> s*a
                u32 a0 = kbase + (u32)((8 * nb0 * LDH) * 2);
                u32 a1 = a0 + (u32)(8 * LDH * 2);
                u32 kb0[4], kb1[4];
                ldsm4(a0, kb0);
                ldsm4(a1, kb1);
                mma_fp(s0a, qa[0], kb0[0], kb0[1]);
                mma_fp(s1a, qa[0], kb1[0], kb1[1]);
                mma_fp(s0a, qa[1], kb0[2], kb0[3]);
                mma_fp(s1a, qa[1], kb1[2], kb1[3]);
                mma_fp(s0a, ql[0], kb0[0], kb0[1]);
                mma_fp(s1a, ql[0], kb1[0], kb1[1]);
                mma_fp(s0a, ql[1], kb0[2], kb0[3]);
                mma_fp(s1a, ql[1], kb1[2], kb1[3]);
            }
            {   // g = 1 -> s*b (independent chains)
                u32 a0 = kbase + (u32)(((8 * nb0 * LDH) + 32) * 2);
                u32 a1 = a0 + (u32)(8 * LDH * 2);
                u32 kb0[4], kb1[4];
                ldsm4(a0, kb0);
                ldsm4(a1, kb1);
                mma_fp(s0b, qa[2], kb0[0], kb0[1]);
                mma_fp(s1b, qa[2], kb1[0], kb1[1]);
                mma_fp(s0b, qa[3], kb0[2], kb0[3]);
                mma_fp(s1b, qa[3], kb1[2], kb1[3]);
                mma_fp(s0b, ql[2], kb0[0], kb0[1]);
                mma_fp(s1b, ql[2], kb1[0], kb1[1]);
                mma_fp(s0b, ql[3], kb0[2], kb0[3]);
                mma_fp(s1b, ql[3], kb1[2], kb1[3]);
            }

            // ---- log2-logits x = 2*CEXP*s + (q + kscaled); mask -> -2e30 ----
            float2 kk0 = *(const float2*)&ksq[8 * nb0 + 2 * (t & 3)];
            float2 kk1 = *(const float2*)&ksq[8 * nb1 + 2 * (t & 3)];
            float x00 = fmaf(s0a[0] + s0b[0], 2.f*CEXP, q0 + kk0.x);
            float x01 = fmaf(s0a[1] + s0b[1], 2.f*CEXP, q0 + kk0.y);
            float x02 = fmaf(s0a[2] + s0b[2], 2.f*CEXP, q1 + kk0.x);
            float x03 = fmaf(s0a[3] + s0b[3], 2.f*CEXP, q1 + kk0.y);
            float x10 = fmaf(s1a[0] + s1b[0], 2.f*CEXP, q0 + kk1.x);
            float x11 = fmaf(s1a[1] + s1b[1], 2.f*CEXP, q0 + kk1.y);
            float x12 = fmaf(s1a[2] + s1b[2], 2.f*CEXP, q1 + kk1.x);
            float x13 = fmaf(s1a[3] + s1b[3], 2.f*CEXP, q1 + kk1.y);
            if (diag) {
                int n0e = n0 + 8 * nb0 + 2 * (t & 3);
                int n1e = n0 + 8 * nb1 + 2 * (t & 3);
                if (n0e     > m_r0) x00 = -2e30f;
                if (n0e + 1 > m_r0) x01 = -2e30f;
                if (n0e     > m_r1) x02 = -2e30f;
                if (n0e + 1 > m_r1) x03 = -2e30f;
                if (n1e     > m_r0) x10 = -2e30f;
                if (n1e + 1 > m_r0) x11 = -2e30f;
                if (n1e     > m_r1) x12 = -2e30f;
                if (n1e + 1 > m_r1) x13 = -2e30f;
            }

            // ---- online row max (quad-wide) + lazy rescale ----
            float qm0 = fmaxf(fmaxf(x00, x01), fmaxf(x10, x11));
            float qm1 = fmaxf(fmaxf(x02, x03), fmaxf(x12, x13));
            qm0 = fmaxf(qm0, __shfl_xor_sync(0xffffffffu, qm0, 1));
            qm0 = fmaxf(qm0, __shfl_xor_sync(0xffffffffu, qm0, 2));
            qm1 = fmaxf(qm1, __shfl_xor_sync(0xffffffffu, qm1, 1));
            qm1 = fmaxf(qm1, __shfl_xor_sync(0xffffffffu, qm1, 2));
            if (qm0 > M0) {
                float f = ex2(M0 - qm0);
                M0 = qm0;
                l0 *= f;
#pragma unroll
                for (int nd = 0; nd < 8; nd++) { o[nd][0] *= f; o[nd][1] *= f; }
            }
            if (qm1 > M1) {
                float f = ex2(M1 - qm1);
                M1 = qm1;
                l1 *= f;
#pragma unroll
                for (int nd = 0; nd < 8; nd++) { o[nd][2] *= f; o[nd][3] *= f; }
            }

            // ---- p = ex2(x - M); accumulate l; pack fp16 P fragment ----
            float p00 = ex2(x00 - M0), p01 = ex2(x01 - M0);
            float p02 = ex2(x02 - M1), p03 = ex2(x03 - M1);
            float p10 = ex2(x10 - M0), p11 = ex2(x11 - M0);
            float p12 = ex2(x12 - M1), p13 = ex2(x13 - M1);
            l0 += (p00 + p01) + (p10 + p11);
            l1 += (p02 + p03) + (p12 + p13);

            u32 pha[4];
            pha[0] = bits2h(__floats2half2_rn(p00, p01));
            pha[1] = bits2h(__floats2half2_rn(p02, p03));
            pha[2] = bits2h(__floats2half2_rn(p10, p11));
            pha[3] = bits2h(__floats2half2_rn(p12, p13));

            // ---- PV(p): fp16 single pass, ldsm ping-pong ----
            const u32 vq = vbase + (u32)(16 * p * LDH * 2);
            u32 vhp[2][4];
            ldsm4t(vq, vhp[0]);
#pragma unroll
            for (int pr = 0; pr < 4; pr++) {
                const int cur = pr & 1;
                if (pr < 3)
                    ldsm4t(vq + (u32)((16 * (pr + 1)) * 2), vhp[cur ^ 1]);
                const int nd0 = 2 * pr, nd1 = nd0 + 1;
                mma_fp(o[nd0], pha, vhp[cur][0], vhp[cur][1]);
                mma_fp(o[nd1], pha, vhp[cur][2], vhp[cur][3]);
            }
        }
    }

    // ---- reduce l across the 4-lane quad sharing each row ----
    l0 += __shfl_xor_sync(0xffffffffu, l0, 1);
    l0 += __shfl_xor_sync(0xffffffffu, l0, 2);
    l1 += __shfl_xor_sync(0xffffffffu, l1, 1);
    l1 += __shfl_xor_sync(0xffffffffu, l1, 2);
    const float inv0 = 1.0f / l0;
    const float inv1 = 1.0f / l1;

    // ---- write O ----
#pragma unroll
    for (int nd = 0; nd < 8; nd++) {
        int dcol = 8 * nd + 2 * (t & 3);
        *(float2*)&Oh[(size_t)m_r0 * D_ + dcol] =
            make_float2(o[nd][0] * inv0, o[nd][1] * inv0);
        *(float2*)&Oh[(size_t)m_r1 * D_ + dcol] =
            make_float2(o[nd][2] * inv1, o[nd][3] * inv1);
    }
}

extern "C" void kernel_launch(void* const* d_in, const int* in_sizes, int n_in,
                              void* d_out, int out_size)
{
    const float* q = (const float*)d_in[0];
    const float* k = (const float*)d_in[1];
    const float* v = (const float*)d_in[2];
    float* o = (float*)d_out;
    (void)in_sizes; (void)n_in; (void)out_size;

    prep_kernel<<<TOT4 / 256, 256>>>(k, v);

    cudaFuncSetAttribute(rbf_attn_mma,
                         cudaFuncAttributeMaxDynamicSharedMemorySize, SMEM_BYTES);

    dim3 grid(N_ / BM, 32);
    rbf_attn_mma<<<grid, NTH, SMEM_BYTES>>>(q, o);
}